// round 8
// baseline (speedup 1.0000x reference)
#include <cuda_runtime.h>

#define B_DIM 1024
#define T_DIM 256
#define D_DIM 64
#define H_DIM 128
#define GH 256          // 2H
#define XCOLS 384       // 256 gate cols + 128 cand cols
#define RROWS 2
#define NGROUPS (B_DIM / RROWS)   // 512

// Scratch (device globals: no allocation allowed).
static __device__ float g_Xbuf[(size_t)B_DIM * T_DIM * XCOLS]; // ~402 MB
static __device__ int   g_perm[B_DIM];
static __device__ int   g_counter;

typedef unsigned long long ull;

__device__ __forceinline__ float fast_sigmoid(float z) {
    return __fdividef(1.0f, 1.0f + __expf(-z));
}
__device__ __forceinline__ float fast_tanh(float z) {
    return 1.0f - __fdividef(2.0f, __expf(2.0f * z) + 1.0f);
}

// packed fp32x2 helpers (Blackwell FFMA2 — PTX-only, exact fp32)
__device__ __forceinline__ void ffma2(ull& acc, ull a, ull b) {
    asm("fma.rn.f32x2 %0, %1, %2, %0;" : "+l"(acc) : "l"(a), "l"(b));
}
__device__ __forceinline__ ull pack2(float lo, float hi) {
    ull r;
    asm("mov.b64 %0, {%1, %2};" : "=l"(r) : "f"(lo), "f"(hi));
    return r;
}
__device__ __forceinline__ ull splat2(float v) {
    ull r;
    asm("mov.b64 %0, {%1, %1};" : "=l"(r) : "f"(v));
    return r;
}
__device__ __forceinline__ float hsum2(ull p) {
    float lo, hi;
    asm("mov.b64 {%0, %1}, %2;" : "=f"(lo), "=f"(hi) : "l"(p));
    return lo + hi;
}
__device__ __forceinline__ ull fadd2(ull a, ull b) {
    ull r;
    asm("add.rn.f32x2 %0, %1, %2;" : "=l"(r) : "l"(a), "l"(b));
    return r;
}

// ---------------------------------------------------------------------------
// K0: counting sort rows by seq_len (descending, LPT) + reset work counter.
// ---------------------------------------------------------------------------
__global__ void sort_kernel(const int* __restrict__ seq_lens) {
    __shared__ int hist[256];
    __shared__ int offs[256];
    int tid = threadIdx.x;
    hist[tid] = 0;
    __syncthreads();
    for (int r = tid; r < B_DIM; r += 256) {
        int L = seq_lens[r];
        L = min(max(L, 0), 255);
        atomicAdd(&hist[L], 1);
    }
    __syncthreads();
    if (tid == 0) {
        int run = 0;
        for (int k = 255; k >= 0; k--) { offs[k] = run; run += hist[k]; }
        g_counter = 0;
    }
    __syncthreads();
    for (int r = tid; r < B_DIM; r += 256) {
        int L = seq_lens[r];
        L = min(max(L, 0), 255);
        int pos = atomicAdd(&offs[L], 1);
        g_perm[pos] = r;
    }
}

// ---------------------------------------------------------------------------
// K1: projection (FFMA2).  Xbuf[b,t,0:256] = emb @ Wg_x + gb,
//                          Xbuf[b,t,256:384] = emb @ Wc_x + cb.
// 512 threads, tile = 64 t-rows x 384 cols.
// ---------------------------------------------------------------------------
__global__ void __launch_bounds__(512) proj_kernel(
    const int* __restrict__ item_his,
    const int* __restrict__ seq_lens,
    const float* __restrict__ embedding,
    const float* __restrict__ gate_kernel,
    const float* __restrict__ gate_bias,
    const float* __restrict__ cand_kernel,
    const float* __restrict__ cand_bias)
{
    extern __shared__ float sm[];
    float* Wx = sm;                    // [64][384]
    float* xs = Wx + 64 * XCOLS;       // [64][64]
    float* bs = xs + 64 * 64;          // [384]
    __shared__ int items_s[64];

    int b  = blockIdx.y;
    int t0 = blockIdx.x * 64;
    int len = seq_lens[b];
    if (t0 >= len) return;
    int tid = threadIdx.x;

    for (int idx = tid; idx < 64 * GH; idx += 512) {
        int k = idx >> 8, c = idx & 255;
        Wx[k * XCOLS + c] = gate_kernel[k * GH + c];
    }
    for (int idx = tid; idx < 64 * H_DIM; idx += 512) {
        int k = idx >> 7, c = idx & 127;
        Wx[k * XCOLS + 256 + c] = cand_kernel[k * H_DIM + c];
    }
    if (tid < 256) bs[tid] = gate_bias[tid];
    else if (tid < 384) bs[tid] = cand_bias[tid - 256];
    if (tid < 64) items_s[tid] = item_his[b * T_DIM + t0 + tid];
    __syncthreads();

    for (int e = tid; e < 64 * 64; e += 512) {
        int rr = e >> 6, k = e & 63;
        xs[e] = embedding[items_s[rr] * 64 + k];
    }
    __syncthreads();

    int tc = tid & 31;     // column pair base = 2*tc
    int tr = tid >> 5;     // row base (0..15), rows tr + 16*ri
    ull acc[4][6];
    #pragma unroll
    for (int ri = 0; ri < 4; ri++)
        #pragma unroll
        for (int ci = 0; ci < 6; ci++) acc[ri][ci] = 0ULL;

    #pragma unroll 4
    for (int k = 0; k < 64; k++) {
        ull A0 = splat2(xs[(tr + 0)  * 64 + k]);
        ull A1 = splat2(xs[(tr + 16) * 64 + k]);
        ull A2 = splat2(xs[(tr + 32) * 64 + k]);
        ull A3 = splat2(xs[(tr + 48) * 64 + k]);
        const float* wrow = Wx + k * XCOLS + 2 * tc;
        #pragma unroll
        for (int ci = 0; ci < 6; ci++) {
            ull w = *(const ull*)(wrow + 64 * ci);
            ffma2(acc[0][ci], A0, w);
            ffma2(acc[1][ci], A1, w);
            ffma2(acc[2][ci], A2, w);
            ffma2(acc[3][ci], A3, w);
        }
    }

    #pragma unroll
    for (int ri = 0; ri < 4; ri++) {
        int t = t0 + tr + 16 * ri;
        float* dst = g_Xbuf + (size_t)(b * T_DIM + t) * XCOLS;
        #pragma unroll
        for (int ci = 0; ci < 6; ci++) {
            int c = 2 * tc + 64 * ci;
            ull bias2 = *(const ull*)(bs + c);
            *(ull*)(dst + c) = fadd2(acc[ri][ci], bias2);
        }
    }
}

// ---------------------------------------------------------------------------
// K2: persistent GRU — TWO interleaved 2-row groups (A, B) per CTA, shared
// register-resident weights, 3-phase software pipeline:
//   phase1: gateA(t)      + candB_part(t-1)
//   phase2: candB_comb    + candA_part(t)
//   phase3: candA_comb    + gateB(t)
// 256 threads: gate thread j -> col j (2 rows); cand thread (i, half) ->
// k-half partials for 2 rows, owner row = half after exchange.
// ---------------------------------------------------------------------------
__global__ void __launch_bounds__(256, 1) gru_kernel(
    const int* __restrict__ seq_lens,
    const float* __restrict__ gate_kernel,
    const float* __restrict__ cand_kernel,
    float* __restrict__ out)
{
    __shared__ float h_s[2][2 * H_DIM];
    __shared__ float rh_s[2][2 * H_DIM];
    __shared__ float u_s[2][2 * H_DIM];
    __shared__ float part_s[2][2 * H_DIM];
    __shared__ int s_g;
    __shared__ int s_b[2][2];
    __shared__ int s_len[2][2];

    int tid  = threadIdx.x;
    int j    = tid;
    int i    = tid & 127;
    int half = tid >> 7;

    // Gate weight column j (64 packed k-pairs), shared by both groups.
    ull wg[64];
    #pragma unroll
    for (int k2 = 0; k2 < 64; k2++) {
        wg[k2] = pack2(gate_kernel[(D_DIM + 2 * k2)     * GH + j],
                       gate_kernel[(D_DIM + 2 * k2 + 1) * GH + j]);
    }
    // Cand weight half-column (32 packed k-pairs), k in [64*half, 64*half+64).
    ull wc[32];
    #pragma unroll
    for (int k2 = 0; k2 < 32; k2++) {
        int k = 64 * half + 2 * k2;
        wc[k2] = pack2(cand_kernel[(D_DIM + k)     * H_DIM + i],
                       cand_kernel[(D_DIM + k + 1) * H_DIM + i]);
    }

    while (true) {
        if (tid == 0) s_g = atomicAdd(&g_counter, 2);
        __syncthreads();
        int g = s_g;
        if (g >= NGROUPS) break;

        if (tid < 4) {
            int grp = tid >> 1, r = tid & 1;
            int row = g_perm[(g + grp) * RROWS + r];
            s_b[grp][r]   = row;
            s_len[grp][r] = min(max(seq_lens[row], 0), T_DIM);
        }
        h_s[0][tid] = 0.0f;
        h_s[1][tid] = 0.0f;
        __syncthreads();

        int LA = max(s_len[0][0], s_len[0][1]);
        int LB = max(s_len[1][0], s_len[1][1]);
        int Lloop = max(LA, LB + 1);

        int agx0 = s_b[0][0] * (T_DIM * XCOLS) + j;
        int agx1 = s_b[0][1] * (T_DIM * XCOLS) + j;
        int bgx0 = s_b[1][0] * (T_DIM * XCOLS) + j;
        int bgx1 = s_b[1][1] * (T_DIM * XCOLS) + j;
        int acx  = s_b[0][half] * (T_DIM * XCOLS) + 256 + i;
        int bcx  = s_b[1][half] * (T_DIM * XCOLS) + 256 + i;
        int lenA_own = s_len[0][half];
        int lenB_own = s_len[1][half];

        float ownA = 0.f, ownB = 0.f, vcA = 0.f, vcB = 0.f;

        for (int t = 0; t < Lloop; t++) {
            int tb = t - 1;
            bool doA  = t < LA;
            bool doB  = (tb >= 0) && (tb < LB);
            bool doGB = t < LB;

            // ---------- phase 1: gateA(t) + candB_part(tb) ----------
            if (doA) {
                float vg0 = g_Xbuf[agx0 + t * XCOLS];
                float vg1 = g_Xbuf[agx1 + t * XCOLS];
                ull a0 = pack2(vg0, 0.f), a1 = pack2(vg1, 0.f);
                const ulonglong2* hh0 = (const ulonglong2*)(h_s[0]);
                const ulonglong2* hh1 = (const ulonglong2*)(h_s[0] + H_DIM);
                #pragma unroll
                for (int k4 = 0; k4 < 32; k4++) {
                    ulonglong2 v0 = hh0[k4];
                    ffma2(a0, v0.x, wg[2 * k4]); ffma2(a0, v0.y, wg[2 * k4 + 1]);
                    ulonglong2 v1 = hh1[k4];
                    ffma2(a1, v1.x, wg[2 * k4]); ffma2(a1, v1.y, wg[2 * k4 + 1]);
                }
                float s0 = fast_sigmoid(hsum2(a0));
                float s1 = fast_sigmoid(hsum2(a1));
                if (j < H_DIM) {
                    rh_s[0][j]         = s0 * h_s[0][j];
                    rh_s[0][H_DIM + j] = s1 * h_s[0][H_DIM + j];
                } else {
                    u_s[0][i]          = s0;
                    u_s[0][H_DIM + i]  = s1;
                }
            }
            if (doB) {
                vcB = g_Xbuf[bcx + tb * XCOLS];
                ull p0 = 0ULL, p1 = 0ULL;
                const ulonglong2* r0 = (const ulonglong2*)(rh_s[1] + half * 64);
                const ulonglong2* r1 = (const ulonglong2*)(rh_s[1] + H_DIM + half * 64);
                #pragma unroll
                for (int k4 = 0; k4 < 16; k4++) {
                    ulonglong2 v0 = r0[k4];
                    ffma2(p0, v0.x, wc[2 * k4]); ffma2(p0, v0.y, wc[2 * k4 + 1]);
                    ulonglong2 v1 = r1[k4];
                    ffma2(p1, v1.x, wc[2 * k4]); ffma2(p1, v1.y, wc[2 * k4 + 1]);
                }
                float f0 = hsum2(p0), f1 = hsum2(p1);
                if (half == 0) { part_s[1][H_DIM + i] = f1; ownB = f0; }
                else           { part_s[1][i]         = f0; ownB = f1; }
            }
            __syncthreads();

            // ---------- phase 2: candB_combine(tb) + candA_part(t) ----------
            if (doB) {
                float c  = fast_tanh(ownB + part_s[1][half * H_DIM + i] + vcB);
                float uu = u_s[1][half * H_DIM + i];
                float hv = h_s[1][half * H_DIM + i];
                if (tb < lenB_own) h_s[1][half * H_DIM + i] = fmaf(uu, hv - c, c);
            }
            if (doA) {
                vcA = g_Xbuf[acx + t * XCOLS];
                ull p0 = 0ULL, p1 = 0ULL;
                const ulonglong2* r0 = (const ulonglong2*)(rh_s[0] + half * 64);
                const ulonglong2* r1 = (const ulonglong2*)(rh_s[0] + H_DIM + half * 64);
                #pragma unroll
                for (int k4 = 0; k4 < 16; k4++) {
                    ulonglong2 v0 = r0[k4];
                    ffma2(p0, v0.x, wc[2 * k4]); ffma2(p0, v0.y, wc[2 * k4 + 1]);
                    ulonglong2 v1 = r1[k4];
                    ffma2(p1, v1.x, wc[2 * k4]); ffma2(p1, v1.y, wc[2 * k4 + 1]);
                }
                float f0 = hsum2(p0), f1 = hsum2(p1);
                if (half == 0) { part_s[0][H_DIM + i] = f1; ownA = f0; }
                else           { part_s[0][i]         = f0; ownA = f1; }
            }
            __syncthreads();

            // ---------- phase 3: candA_combine(t) + gateB(t) ----------
            if (doA) {
                float c  = fast_tanh(ownA + part_s[0][half * H_DIM + i] + vcA);
                float uu = u_s[0][half * H_DIM + i];
                float hv = h_s[0][half * H_DIM + i];
                if (t < lenA_own) h_s[0][half * H_DIM + i] = fmaf(uu, hv - c, c);
            }
            if (doGB) {
                float vg0 = g_Xbuf[bgx0 + t * XCOLS];
                float vg1 = g_Xbuf[bgx1 + t * XCOLS];
                ull a0 = pack2(vg0, 0.f), a1 = pack2(vg1, 0.f);
                const ulonglong2* hh0 = (const ulonglong2*)(h_s[1]);
                const ulonglong2* hh1 = (const ulonglong2*)(h_s[1] + H_DIM);
                #pragma unroll
                for (int k4 = 0; k4 < 32; k4++) {
                    ulonglong2 v0 = hh0[k4];
                    ffma2(a0, v0.x, wg[2 * k4]); ffma2(a0, v0.y, wg[2 * k4 + 1]);
                    ulonglong2 v1 = hh1[k4];
                    ffma2(a1, v1.x, wg[2 * k4]); ffma2(a1, v1.y, wg[2 * k4 + 1]);
                }
                float s0 = fast_sigmoid(hsum2(a0));
                float s1 = fast_sigmoid(hsum2(a1));
                if (j < H_DIM) {
                    rh_s[1][j]         = s0 * h_s[1][j];
                    rh_s[1][H_DIM + j] = s1 * h_s[1][H_DIM + j];
                } else {
                    u_s[1][i]          = s0;
                    u_s[1][H_DIM + i]  = s1;
                }
            }
            __syncthreads();
        }

        out[s_b[0][half] * H_DIM + i] = h_s[0][half * H_DIM + i];
        out[s_b[1][half] * H_DIM + i] = h_s[1][half * H_DIM + i];
        __syncthreads();
    }
}

// ---------------------------------------------------------------------------
extern "C" void kernel_launch(void* const* d_in, const int* in_sizes, int n_in,
                              void* d_out, int out_size) {
    (void)in_sizes; (void)n_in; (void)out_size;
    const int*   item_his    = (const int*)  d_in[0];
    const int*   seq_lens    = (const int*)  d_in[1];
    const float* embedding   = (const float*)d_in[2];
    const float* gate_kernel = (const float*)d_in[3];
    const float* gate_bias   = (const float*)d_in[4];
    const float* cand_kernel = (const float*)d_in[5];
    const float* cand_bias   = (const float*)d_in[6];
    float*       out         = (float*)d_out;

    const int smem_proj = (64 * XCOLS + 64 * 64 + XCOLS) * 4;   // ~116 KB
    cudaFuncSetAttribute(proj_kernel, cudaFuncAttributeMaxDynamicSharedMemorySize, smem_proj);

    sort_kernel<<<1, 256>>>(seq_lens);
    proj_kernel<<<dim3(T_DIM / 64, B_DIM), 512, smem_proj>>>(
        item_his, seq_lens, embedding, gate_kernel, gate_bias, cand_kernel, cand_bias);
    gru_kernel<<<148, 256>>>(seq_lens, gate_kernel, cand_kernel, out);
}

// round 9
// speedup vs baseline: 1.2194x; 1.2194x over previous
#include <cuda_runtime.h>

#define B_DIM 1024
#define T_DIM 256
#define D_DIM 64
#define H_DIM 128
#define GH 256          // 2H
#define XCOLS 384       // 256 gate cols + 128 cand cols
#define RROWS 4
#define NGROUPS (B_DIM / RROWS)   // 256
#define XPAD 68         // x smem stride (words): conflict-free A-frag loads
#define WPAD 388        // W smem stride (words): conflict-free B-frag loads

// Scratch (device globals: no allocation allowed).
static __device__ float g_Xbuf[(size_t)B_DIM * T_DIM * XCOLS]; // ~402 MB
static __device__ int   g_perm[B_DIM];
static __device__ int   g_counter;

typedef unsigned long long ull;

__device__ __forceinline__ float fast_sigmoid(float z) {
    return __fdividef(1.0f, 1.0f + __expf(-z));
}
__device__ __forceinline__ float fast_tanh(float z) {
    return 1.0f - __fdividef(2.0f, __expf(2.0f * z) + 1.0f);
}

// packed fp32x2 helpers (exact fp32)
__device__ __forceinline__ void ffma2(ull& acc, ull a, ull b) {
    asm("fma.rn.f32x2 %0, %1, %2, %0;" : "+l"(acc) : "l"(a), "l"(b));
}
__device__ __forceinline__ ull pack2(float lo, float hi) {
    ull r;
    asm("mov.b64 %0, {%1, %2};" : "=l"(r) : "f"(lo), "f"(hi));
    return r;
}
__device__ __forceinline__ float hsum2(ull p) {
    float lo, hi;
    asm("mov.b64 {%0, %1}, %2;" : "=f"(lo), "=f"(hi) : "l"(p));
    return lo + hi;
}
__device__ __forceinline__ unsigned f2tf32(float f) {
    unsigned u;
    asm("cvt.rna.tf32.f32 %0, %1;" : "=r"(u) : "f"(f));
    return u;
}
__device__ __forceinline__ void mma_tf32(float& c0, float& c1, float& c2, float& c3,
                                         unsigned a0, unsigned a1, unsigned a2, unsigned a3,
                                         unsigned b0, unsigned b1) {
    asm("mma.sync.aligned.m16n8k8.row.col.f32.tf32.tf32.f32 "
        "{%0,%1,%2,%3}, {%4,%5,%6,%7}, {%8,%9}, {%0,%1,%2,%3};"
        : "+f"(c0), "+f"(c1), "+f"(c2), "+f"(c3)
        : "r"(a0), "r"(a1), "r"(a2), "r"(a3), "r"(b0), "r"(b1));
}

// ---------------------------------------------------------------------------
// K0: counting sort rows by seq_len (descending, LPT) + reset work counter.
// ---------------------------------------------------------------------------
__global__ void sort_kernel(const int* __restrict__ seq_lens) {
    __shared__ int hist[256];
    __shared__ int offs[256];
    int tid = threadIdx.x;
    hist[tid] = 0;
    __syncthreads();
    for (int r = tid; r < B_DIM; r += 256) {
        int L = seq_lens[r];
        L = min(max(L, 0), 255);
        atomicAdd(&hist[L], 1);
    }
    __syncthreads();
    if (tid == 0) {
        int run = 0;
        for (int k = 255; k >= 0; k--) { offs[k] = run; run += hist[k]; }
        g_counter = 0;
    }
    __syncthreads();
    for (int r = tid; r < B_DIM; r += 256) {
        int L = seq_lens[r];
        L = min(max(L, 0), 255);
        int pos = atomicAdd(&offs[L], 1);
        g_perm[pos] = r;
    }
}

// ---------------------------------------------------------------------------
// K1: projection via tf32 tensor cores.
//   Xbuf[b,t,0:256] = emb @ Wg_x + gb ; Xbuf[b,t,256:384] = emb @ Wc_x + cb
// 512 threads = 16 warps as 4(M) x 4(N): warp tile = 16 rows x 96 cols, K=64.
// ---------------------------------------------------------------------------
__global__ void __launch_bounds__(512) proj_kernel(
    const int* __restrict__ item_his,
    const int* __restrict__ seq_lens,
    const float* __restrict__ embedding,
    const float* __restrict__ gate_kernel,
    const float* __restrict__ gate_bias,
    const float* __restrict__ cand_kernel,
    const float* __restrict__ cand_bias)
{
    extern __shared__ unsigned smu[];
    unsigned* xs = smu;                      // [64][XPAD] tf32 bits
    unsigned* Wt = xs + 64 * XPAD;           // [64][WPAD] tf32 bits
    float*    bs = (float*)(Wt + 64 * WPAD); // [384]
    __shared__ int items_s[64];

    int b  = blockIdx.y;
    int t0 = blockIdx.x * 64;
    int len = seq_lens[b];
    if (t0 >= len) return;
    int tid = threadIdx.x;

    // stage tf32 weights + biases
    for (int idx = tid; idx < 64 * GH; idx += 512) {
        int k = idx >> 8, c = idx & 255;
        Wt[k * WPAD + c] = f2tf32(gate_kernel[k * GH + c]);
    }
    for (int idx = tid; idx < 64 * H_DIM; idx += 512) {
        int k = idx >> 7, c = idx & 127;
        Wt[k * WPAD + 256 + c] = f2tf32(cand_kernel[k * H_DIM + c]);
    }
    if (tid < 256) bs[tid] = gate_bias[tid];
    else if (tid < 384) bs[tid] = cand_bias[tid - 256];
    if (tid < 64) items_s[tid] = item_his[b * T_DIM + t0 + tid];
    __syncthreads();

    // gather embedding rows (tf32-rounded)
    for (int e = tid; e < 64 * 64; e += 512) {
        int rr = e >> 6, k = e & 63;
        xs[rr * XPAD + k] = f2tf32(embedding[items_s[rr] * 64 + k]);
    }
    __syncthreads();

    int warp = tid >> 5, lane = tid & 31;
    int wm = warp & 3;                  // m-tile: rows 16*wm..
    int wn = warp >> 2;                 // n-base 96*wn
    int rbase = wm * 16;
    int nbase = wn * 96;

    float c[12][4];
    #pragma unroll
    for (int nt = 0; nt < 12; nt++)
        #pragma unroll
        for (int q = 0; q < 4; q++) c[nt][q] = 0.0f;

    int ar = rbase + (lane >> 2);
    int ac0 = lane & 3;

    #pragma unroll
    for (int k0 = 0; k0 < 8; k0++) {
        int ka = k0 * 8;
        unsigned a0 = xs[ar * XPAD + ka + ac0];
        unsigned a1 = xs[(ar + 8) * XPAD + ka + ac0];
        unsigned a2 = xs[ar * XPAD + ka + ac0 + 4];
        unsigned a3 = xs[(ar + 8) * XPAD + ka + ac0 + 4];
        const unsigned* Wrow0 = Wt + (ka + (lane & 3)) * WPAD + (lane >> 2);
        const unsigned* Wrow1 = Wrow0 + 4 * WPAD;
        #pragma unroll
        for (int nt = 0; nt < 12; nt++) {
            unsigned b0 = Wrow0[nbase + nt * 8];
            unsigned b1 = Wrow1[nbase + nt * 8];
            mma_tf32(c[nt][0], c[nt][1], c[nt][2], c[nt][3], a0, a1, a2, a3, b0, b1);
        }
    }

    // epilogue: c0,c1 -> (row, col..col+1), c2,c3 -> (row+8, col..col+1)
    int row0 = rbase + (lane >> 2);
    #pragma unroll
    for (int nt = 0; nt < 12; nt++) {
        int col = nbase + nt * 8 + 2 * (lane & 3);
        float2 v01 = make_float2(c[nt][0] + bs[col], c[nt][1] + bs[col + 1]);
        float2 v23 = make_float2(c[nt][2] + bs[col], c[nt][3] + bs[col + 1]);
        float* d0 = g_Xbuf + (size_t)(b * T_DIM + t0 + row0) * XCOLS + col;
        float* d1 = g_Xbuf + (size_t)(b * T_DIM + t0 + row0 + 8) * XCOLS + col;
        *(float2*)d0 = v01;
        *(float2*)d1 = v23;
    }
}

// ---------------------------------------------------------------------------
// K2: persistent GRU — register weights, 2 barriers/step, shfl exchange.
// 256 threads, one 4-row group at a time.
//   gate: thread j holds Ug col j (64 packed f32x2 regs), col j x 4 rows.
//   cand: thread pair (2i, 2i+1): lane parity kh = k-half; 4-row half-k
//         partials; combine with shfl.xor(1); kh picks owned row pair.
// ---------------------------------------------------------------------------
__global__ void __launch_bounds__(256, 1) gru_kernel(
    const int* __restrict__ seq_lens,
    const float* __restrict__ gate_kernel,
    const float* __restrict__ cand_kernel,
    float* __restrict__ out)
{
    __shared__ float h_s[RROWS * H_DIM];
    __shared__ float rh_s[RROWS * H_DIM];
    __shared__ float u_s[RROWS * H_DIM];
    __shared__ int s_g;
    __shared__ int s_b[RROWS];
    __shared__ int s_len[RROWS];

    int tid = threadIdx.x;
    int j   = tid;              // gate column
    int i   = tid >> 1;         // cand column
    int kh  = tid & 1;          // cand k-half & owned row pair

    // Gate weight column j (64 packed k-pairs)
    ull wg[64];
    #pragma unroll
    for (int k2 = 0; k2 < 64; k2++) {
        wg[k2] = pack2(gate_kernel[(D_DIM + 2 * k2)     * GH + j],
                       gate_kernel[(D_DIM + 2 * k2 + 1) * GH + j]);
    }
    // Cand weight half-column (32 packed k-pairs), k in [64*kh, 64*kh+64)
    ull wc[32];
    #pragma unroll
    for (int k2 = 0; k2 < 32; k2++) {
        int k = 64 * kh + 2 * k2;
        wc[k2] = pack2(cand_kernel[(D_DIM + k)     * H_DIM + i],
                       cand_kernel[(D_DIM + k + 1) * H_DIM + i]);
    }

    const ulonglong2* h20 = (const ulonglong2*)(h_s);
    const ulonglong2* h21 = h20 + (H_DIM / 4);
    const ulonglong2* h22 = h21 + (H_DIM / 4);
    const ulonglong2* h23 = h22 + (H_DIM / 4);
    const ulonglong2* rh20 = (const ulonglong2*)(rh_s + 0 * H_DIM + kh * 64);
    const ulonglong2* rh21 = (const ulonglong2*)(rh_s + 1 * H_DIM + kh * 64);
    const ulonglong2* rh22 = (const ulonglong2*)(rh_s + 2 * H_DIM + kh * 64);
    const ulonglong2* rh23 = (const ulonglong2*)(rh_s + 3 * H_DIM + kh * 64);
    int rA = 2 * kh, rB = 2 * kh + 1;   // owned rows

    while (true) {
        if (tid == 0) s_g = atomicAdd(&g_counter, 1);
        __syncthreads();
        int g = s_g;
        if (g >= NGROUPS) break;

        if (tid < RROWS) {
            int row = g_perm[g * RROWS + tid];
            s_b[tid]   = row;
            s_len[tid] = min(max(seq_lens[row], 0), T_DIM);
        }
        for (int e = tid; e < RROWS * H_DIM; e += 256) h_s[e] = 0.0f;
        __syncthreads();

        int len0 = s_len[0], len1 = s_len[1], len2 = s_len[2], len3 = s_len[3];
        int L = max(max(len0, len1), max(len2, len3));
        int lenA = s_len[rA];
        int lenB = s_len[rB];

        int x0 = s_b[0] * (T_DIM * XCOLS) + j;
        int x1 = s_b[1] * (T_DIM * XCOLS) + j;
        int x2 = s_b[2] * (T_DIM * XCOLS) + j;
        int x3 = s_b[3] * (T_DIM * XCOLS) + j;
        int xA = s_b[rA] * (T_DIM * XCOLS) + 256 + i;
        int xB = s_b[rB] * (T_DIM * XCOLS) + 256 + i;

        for (int t = 0; t < L; t++) {
            int toff = t * XCOLS;
            float vg0 = g_Xbuf[x0 + toff];
            float vg1 = g_Xbuf[x1 + toff];
            float vg2 = g_Xbuf[x2 + toff];
            float vg3 = g_Xbuf[x3 + toff];
            float vcA = g_Xbuf[xA + toff];
            float vcB = g_Xbuf[xB + toff];

            // gate GEMM (col j, 4 rows)
            ull a0 = pack2(vg0, 0.f);
            ull a1 = pack2(vg1, 0.f);
            ull a2 = pack2(vg2, 0.f);
            ull a3 = pack2(vg3, 0.f);
            #pragma unroll
            for (int k4 = 0; k4 < H_DIM / 4; k4++) {
                ulonglong2 v0 = h20[k4];
                ffma2(a0, v0.x, wg[2 * k4]); ffma2(a0, v0.y, wg[2 * k4 + 1]);
                ulonglong2 v1 = h21[k4];
                ffma2(a1, v1.x, wg[2 * k4]); ffma2(a1, v1.y, wg[2 * k4 + 1]);
                ulonglong2 v2 = h22[k4];
                ffma2(a2, v2.x, wg[2 * k4]); ffma2(a2, v2.y, wg[2 * k4 + 1]);
                ulonglong2 v3 = h23[k4];
                ffma2(a3, v3.x, wg[2 * k4]); ffma2(a3, v3.y, wg[2 * k4 + 1]);
            }
            float s0 = fast_sigmoid(hsum2(a0));
            float s1 = fast_sigmoid(hsum2(a1));
            float s2 = fast_sigmoid(hsum2(a2));
            float s3 = fast_sigmoid(hsum2(a3));

            if (j < H_DIM) {           // r-gate columns 0..127
                rh_s[0 * H_DIM + j] = s0 * h_s[0 * H_DIM + j];
                rh_s[1 * H_DIM + j] = s1 * h_s[1 * H_DIM + j];
                rh_s[2 * H_DIM + j] = s2 * h_s[2 * H_DIM + j];
                rh_s[3 * H_DIM + j] = s3 * h_s[3 * H_DIM + j];
            } else {                   // u-gate columns 128..255
                int jj = j - H_DIM;
                u_s[0 * H_DIM + jj] = s0;
                u_s[1 * H_DIM + jj] = s1;
                u_s[2 * H_DIM + jj] = s2;
                u_s[3 * H_DIM + jj] = s3;
            }
            __syncthreads();

            // cand partials: k in [64*kh, 64*kh+64), all 4 rows
            ull c0 = 0ULL, c1 = 0ULL, c2 = 0ULL, c3 = 0ULL;
            #pragma unroll
            for (int k4 = 0; k4 < 16; k4++) {
                ulonglong2 v0 = rh20[k4];
                ffma2(c0, v0.x, wc[2 * k4]); ffma2(c0, v0.y, wc[2 * k4 + 1]);
                ulonglong2 v1 = rh21[k4];
                ffma2(c1, v1.x, wc[2 * k4]); ffma2(c1, v1.y, wc[2 * k4 + 1]);
                ulonglong2 v2 = rh22[k4];
                ffma2(c2, v2.x, wc[2 * k4]); ffma2(c2, v2.y, wc[2 * k4 + 1]);
                ulonglong2 v3 = rh23[k4];
                ffma2(c3, v3.x, wc[2 * k4]); ffma2(c3, v3.y, wc[2 * k4 + 1]);
            }
            float p0 = hsum2(c0), p1 = hsum2(c1), p2 = hsum2(c2), p3 = hsum2(c3);
            // combine k-halves with partner lane (no barrier)
            float f0 = p0 + __shfl_xor_sync(0xffffffffu, p0, 1);
            float f1 = p1 + __shfl_xor_sync(0xffffffffu, p1, 1);
            float f2 = p2 + __shfl_xor_sync(0xffffffffu, p2, 1);
            float f3 = p3 + __shfl_xor_sync(0xffffffffu, p3, 1);
            float fA = kh ? f2 : f0;
            float fB = kh ? f3 : f1;

            {
                float c  = fast_tanh(fA + vcA);
                float u  = u_s[rA * H_DIM + i];
                float hv = h_s[rA * H_DIM + i];
                float hn = fmaf(u, hv - c, c);   // u*h + (1-u)*c
                if (t < lenA) h_s[rA * H_DIM + i] = hn;
            }
            {
                float c  = fast_tanh(fB + vcB);
                float u  = u_s[rB * H_DIM + i];
                float hv = h_s[rB * H_DIM + i];
                float hn = fmaf(u, hv - c, c);
                if (t < lenB) h_s[rB * H_DIM + i] = hn;
            }
            __syncthreads();
        }

        out[s_b[rA] * H_DIM + i] = h_s[rA * H_DIM + i];
        out[s_b[rB] * H_DIM + i] = h_s[rB * H_DIM + i];
        __syncthreads();
    }
}

// ---------------------------------------------------------------------------
extern "C" void kernel_launch(void* const* d_in, const int* in_sizes, int n_in,
                              void* d_out, int out_size) {
    (void)in_sizes; (void)n_in; (void)out_size;
    const int*   item_his    = (const int*)  d_in[0];
    const int*   seq_lens    = (const int*)  d_in[1];
    const float* embedding   = (const float*)d_in[2];
    const float* gate_kernel = (const float*)d_in[3];
    const float* gate_bias   = (const float*)d_in[4];
    const float* cand_kernel = (const float*)d_in[5];
    const float* cand_bias   = (const float*)d_in[6];
    float*       out         = (float*)d_out;

    const int smem_proj = (64 * XPAD + 64 * WPAD + 384) * 4;   // ~118 KB
    cudaFuncSetAttribute(proj_kernel, cudaFuncAttributeMaxDynamicSharedMemorySize, smem_proj);

    sort_kernel<<<1, 256>>>(seq_lens);
    proj_kernel<<<dim3(T_DIM / 64, B_DIM), 512, smem_proj>>>(
        item_his, seq_lens, embedding, gate_kernel, gate_bias, cand_kernel, cand_bias);
    gru_kernel<<<148, 256>>>(seq_lens, gate_kernel, cand_kernel, out);
}

// round 10
// speedup vs baseline: 1.3571x; 1.1129x over previous
#include <cuda_runtime.h>

#define B_DIM 1024
#define T_DIM 256
#define D_DIM 64
#define H_DIM 128
#define GH 256          // 2H
#define XCOLS 384       // 256 gate cols + 128 cand cols
#define RROWS 4
#define NGROUPS (B_DIM / RROWS)   // 256
#define XPAD 68         // x smem stride (words): conflict-free A-frag loads
#define WPAD 392        // W smem stride (words): 392%32=8 -> conflict-free B-frag loads

// Scratch (device globals: no allocation allowed).
static __device__ float g_Xbuf[(size_t)B_DIM * T_DIM * XCOLS]; // ~402 MB
static __device__ int   g_perm[B_DIM];
static __device__ int   g_counter;

typedef unsigned long long ull;

__device__ __forceinline__ float fast_sigmoid(float z) {
    return __fdividef(1.0f, 1.0f + __expf(-z));
}
__device__ __forceinline__ float fast_tanh(float z) {
    return 1.0f - __fdividef(2.0f, __expf(2.0f * z) + 1.0f);
}

// packed fp32x2 helpers (exact fp32)
__device__ __forceinline__ void ffma2(ull& acc, ull a, ull b) {
    asm("fma.rn.f32x2 %0, %1, %2, %0;" : "+l"(acc) : "l"(a), "l"(b));
}
__device__ __forceinline__ ull pack2(float lo, float hi) {
    ull r;
    asm("mov.b64 %0, {%1, %2};" : "=l"(r) : "f"(lo), "f"(hi));
    return r;
}
__device__ __forceinline__ float hsum2(ull p) {
    float lo, hi;
    asm("mov.b64 {%0, %1}, %2;" : "=f"(lo), "=f"(hi) : "l"(p));
    return lo + hi;
}
__device__ __forceinline__ unsigned f2tf32(float f) {
    unsigned u;
    asm("cvt.rna.tf32.f32 %0, %1;" : "=r"(u) : "f"(f));
    return u;
}
__device__ __forceinline__ void mma_tf32(float& c0, float& c1, float& c2, float& c3,
                                         unsigned a0, unsigned a1, unsigned a2, unsigned a3,
                                         unsigned b0, unsigned b1) {
    asm("mma.sync.aligned.m16n8k8.row.col.f32.tf32.tf32.f32 "
        "{%0,%1,%2,%3}, {%4,%5,%6,%7}, {%8,%9}, {%0,%1,%2,%3};"
        : "+f"(c0), "+f"(c1), "+f"(c2), "+f"(c3)
        : "r"(a0), "r"(a1), "r"(a2), "r"(a3), "r"(b0), "r"(b1));
}

// ---------------------------------------------------------------------------
// K0: counting sort rows by seq_len (descending, LPT) + reset work counter.
// ---------------------------------------------------------------------------
__global__ void sort_kernel(const int* __restrict__ seq_lens) {
    __shared__ int hist[256];
    __shared__ int offs[256];
    int tid = threadIdx.x;
    hist[tid] = 0;
    __syncthreads();
    for (int r = tid; r < B_DIM; r += 256) {
        int L = seq_lens[r];
        L = min(max(L, 0), 255);
        atomicAdd(&hist[L], 1);
    }
    __syncthreads();
    if (tid == 0) {
        int run = 0;
        for (int k = 255; k >= 0; k--) { offs[k] = run; run += hist[k]; }
        g_counter = 0;
    }
    __syncthreads();
    for (int r = tid; r < B_DIM; r += 256) {
        int L = seq_lens[r];
        L = min(max(L, 0), 255);
        int pos = atomicAdd(&offs[L], 1);
        g_perm[pos] = r;
    }
}

// ---------------------------------------------------------------------------
// K1: projection via tf32 tensor cores + smem-staged coalesced epilogue.
//   Xbuf[b,t,0:256] = emb @ Wg_x + gb ; Xbuf[b,t,256:384] = emb @ Wc_x + cb
// 512 threads = 16 warps as 4(M) x 4(N): warp tile = 16 rows x 96 cols, K=64.
// ---------------------------------------------------------------------------
__global__ void __launch_bounds__(512) proj_kernel(
    const int* __restrict__ item_his,
    const int* __restrict__ seq_lens,
    const float* __restrict__ embedding,
    const float* __restrict__ gate_kernel,
    const float* __restrict__ gate_bias,
    const float* __restrict__ cand_kernel,
    const float* __restrict__ cand_bias)
{
    extern __shared__ unsigned smu[];
    unsigned* xs = smu;                      // [64][XPAD] tf32 bits
    unsigned* Wt = xs + 64 * XPAD;           // [64][WPAD] tf32 bits (reused as stage)
    float*    bs = (float*)(Wt + 64 * WPAD); // [384]
    __shared__ int items_s[64];

    int b  = blockIdx.y;
    int t0 = blockIdx.x * 64;
    int len = seq_lens[b];
    if (t0 >= len) return;
    int tid = threadIdx.x;

    // stage tf32 weights + biases
    for (int idx = tid; idx < 64 * GH; idx += 512) {
        int k = idx >> 8, c = idx & 255;
        Wt[k * WPAD + c] = f2tf32(gate_kernel[k * GH + c]);
    }
    for (int idx = tid; idx < 64 * H_DIM; idx += 512) {
        int k = idx >> 7, c = idx & 127;
        Wt[k * WPAD + 256 + c] = f2tf32(cand_kernel[k * H_DIM + c]);
    }
    if (tid < 256) bs[tid] = gate_bias[tid];
    else if (tid < 384) bs[tid] = cand_bias[tid - 256];
    if (tid < 64) items_s[tid] = item_his[b * T_DIM + t0 + tid];
    __syncthreads();

    // gather embedding rows (tf32-rounded)
    for (int e = tid; e < 64 * 64; e += 512) {
        int rr = e >> 6, k = e & 63;
        xs[rr * XPAD + k] = f2tf32(embedding[items_s[rr] * 64 + k]);
    }
    __syncthreads();

    int warp = tid >> 5, lane = tid & 31;
    int wm = warp & 3;                  // m-tile: rows 16*wm..
    int wn = warp >> 2;                 // n-base 96*wn
    int rbase = wm * 16;
    int nbase = wn * 96;

    float c[12][4];
    #pragma unroll
    for (int nt = 0; nt < 12; nt++)
        #pragma unroll
        for (int q = 0; q < 4; q++) c[nt][q] = 0.0f;

    int ar = rbase + (lane >> 2);
    int ac0 = lane & 3;

    #pragma unroll
    for (int k0 = 0; k0 < 8; k0++) {
        int ka = k0 * 8;
        unsigned a0 = xs[ar * XPAD + ka + ac0];
        unsigned a1 = xs[(ar + 8) * XPAD + ka + ac0];
        unsigned a2 = xs[ar * XPAD + ka + ac0 + 4];
        unsigned a3 = xs[(ar + 8) * XPAD + ka + ac0 + 4];
        const unsigned* Wrow0 = Wt + (ka + (lane & 3)) * WPAD + (lane >> 2);
        const unsigned* Wrow1 = Wrow0 + 4 * WPAD;
        #pragma unroll
        for (int nt = 0; nt < 12; nt++) {
            unsigned b0 = Wrow0[nbase + nt * 8];
            unsigned b1 = Wrow1[nbase + nt * 8];
            mma_tf32(c[nt][0], c[nt][1], c[nt][2], c[nt][3], a0, a1, a2, a3, b0, b1);
        }
    }

    // epilogue: stage fragments into smem (reusing Wt), then coalesced store
    __syncthreads();                    // everyone done reading Wt
    float* Xst = (float*)Wt;            // [64][WPAD]
    int row0 = rbase + (lane >> 2);
    #pragma unroll
    for (int nt = 0; nt < 12; nt++) {
        int col = nbase + nt * 8 + 2 * (lane & 3);
        Xst[row0 * WPAD + col]           = c[nt][0];
        Xst[row0 * WPAD + col + 1]       = c[nt][1];
        Xst[(row0 + 8) * WPAD + col]     = c[nt][2];
        Xst[(row0 + 8) * WPAD + col + 1] = c[nt][3];
    }
    __syncthreads();

    const float4* bias4 = (const float4*)bs;
    for (int rr = warp; rr < 64; rr += 16) {
        float4* dst = (float4*)(g_Xbuf + (size_t)(b * T_DIM + t0 + rr) * XCOLS);
        const float4* src = (const float4*)(Xst + rr * WPAD);
        #pragma unroll
        for (int cc = lane; cc < 96; cc += 32) {
            float4 v = src[cc], bb = bias4[cc];
            v.x += bb.x; v.y += bb.y; v.z += bb.z; v.w += bb.w;
            dst[cc] = v;
        }
    }
}

// ---------------------------------------------------------------------------
// K2: persistent GRU — R2 dataflow + REGISTER-RESIDENT weights (R7, best).
// 256 threads, one 4-row group at a time.
//   gate: thread j holds Ug col j (64 packed f32x2 regs), computes col j
//         for all 4 rows. h reads are smem broadcasts.
//   cand: thread (i = j&127, half = j>>7) holds Uc[i][k-half] (32 packed),
//         computes k-half partials for 4 rows; exchange via smem; owner half
//         combines + tanh + h-update for rows 2*half, 2*half+1.
// ---------------------------------------------------------------------------
__global__ void __launch_bounds__(256, 1) gru_kernel(
    const int* __restrict__ seq_lens,
    const float* __restrict__ gate_kernel,
    const float* __restrict__ cand_kernel,
    float* __restrict__ out)
{
    __shared__ float h_s[RROWS * H_DIM];
    __shared__ float rh_s[RROWS * H_DIM];
    __shared__ float u_s[RROWS * H_DIM];
    __shared__ float part_s[RROWS * H_DIM];
    __shared__ int s_g;
    __shared__ int s_b[RROWS];
    __shared__ int s_len[RROWS];

    int tid  = threadIdx.x;
    int j    = tid;             // gate column
    int i    = tid & 127;       // cand column
    int half = tid >> 7;        // cand k-half & row-owner pair

    // Gate weight column j in registers (64 packed k-pairs)
    ull wg[64];
    #pragma unroll
    for (int k2 = 0; k2 < 64; k2++) {
        wg[k2] = pack2(gate_kernel[(D_DIM + 2 * k2)     * GH + j],
                       gate_kernel[(D_DIM + 2 * k2 + 1) * GH + j]);
    }
    // Cand weight half-column in registers (32 packed k-pairs)
    ull wc[32];
    #pragma unroll
    for (int k2 = 0; k2 < 32; k2++) {
        int k = 64 * half + 2 * k2;
        wc[k2] = pack2(cand_kernel[(D_DIM + k)     * H_DIM + i],
                       cand_kernel[(D_DIM + k + 1) * H_DIM + i]);
    }

    const ulonglong2* h20 = (const ulonglong2*)(h_s);
    const ulonglong2* h21 = h20 + (H_DIM / 4);
    const ulonglong2* h22 = h21 + (H_DIM / 4);
    const ulonglong2* h23 = h22 + (H_DIM / 4);
    const ulonglong2* rh20 = (const ulonglong2*)(rh_s + 0 * H_DIM + half * 64);
    const ulonglong2* rh21 = (const ulonglong2*)(rh_s + 1 * H_DIM + half * 64);
    const ulonglong2* rh22 = (const ulonglong2*)(rh_s + 2 * H_DIM + half * 64);
    const ulonglong2* rh23 = (const ulonglong2*)(rh_s + 3 * H_DIM + half * 64);
    float* hA = h_s + (2 * half) * H_DIM;      // owned rows
    float* hB = hA + H_DIM;

    while (true) {
        if (tid == 0) s_g = atomicAdd(&g_counter, 1);
        __syncthreads();
        int g = s_g;
        if (g >= NGROUPS) break;

        if (tid < RROWS) {
            int row = g_perm[g * RROWS + tid];
            s_b[tid]   = row;
            s_len[tid] = min(max(seq_lens[row], 0), T_DIM);
        }
        for (int e = tid; e < RROWS * H_DIM; e += 256) h_s[e] = 0.0f;
        __syncthreads();

        int len0 = s_len[0], len1 = s_len[1], len2 = s_len[2], len3 = s_len[3];
        int L = max(max(len0, len1), max(len2, len3));
        int lenA = half ? len2 : len0;
        int lenB = half ? len3 : len1;

        // 32-bit element offsets into g_Xbuf (100M floats < 2^31)
        int x0 = s_b[0] * (T_DIM * XCOLS) + j;
        int x1 = s_b[1] * (T_DIM * XCOLS) + j;
        int x2 = s_b[2] * (T_DIM * XCOLS) + j;
        int x3 = s_b[3] * (T_DIM * XCOLS) + j;
        int xA = s_b[2 * half]     * (T_DIM * XCOLS) + 256 + i;
        int xB = s_b[2 * half + 1] * (T_DIM * XCOLS) + 256 + i;

        for (int t = 0; t < L; t++) {
            int toff = t * XCOLS;
            // early global loads (consumed after the k-loops)
            float vg0 = g_Xbuf[x0 + toff];
            float vg1 = g_Xbuf[x1 + toff];
            float vg2 = g_Xbuf[x2 + toff];
            float vg3 = g_Xbuf[x3 + toff];
            float vcA = g_Xbuf[xA + toff];
            float vcB = g_Xbuf[xB + toff];

            // gate GEMM (col j, 4 rows) — weights in regs, h broadcast LDS
            ull a0 = pack2(vg0, 0.f), a1 = pack2(vg1, 0.f);
            ull a2 = pack2(vg2, 0.f), a3 = pack2(vg3, 0.f);
            #pragma unroll
            for (int k4 = 0; k4 < H_DIM / 4; k4++) {
                ulonglong2 v0 = h20[k4];
                ffma2(a0, v0.x, wg[2 * k4]); ffma2(a0, v0.y, wg[2 * k4 + 1]);
                ulonglong2 v1 = h21[k4];
                ffma2(a1, v1.x, wg[2 * k4]); ffma2(a1, v1.y, wg[2 * k4 + 1]);
                ulonglong2 v2 = h22[k4];
                ffma2(a2, v2.x, wg[2 * k4]); ffma2(a2, v2.y, wg[2 * k4 + 1]);
                ulonglong2 v3 = h23[k4];
                ffma2(a3, v3.x, wg[2 * k4]); ffma2(a3, v3.y, wg[2 * k4 + 1]);
            }
            float s0 = fast_sigmoid(hsum2(a0));
            float s1 = fast_sigmoid(hsum2(a1));
            float s2 = fast_sigmoid(hsum2(a2));
            float s3 = fast_sigmoid(hsum2(a3));

            if (half == 0) {           // r-gate columns 0..127
                rh_s[0 * H_DIM + j] = s0 * h_s[0 * H_DIM + j];
                rh_s[1 * H_DIM + j] = s1 * h_s[1 * H_DIM + j];
                rh_s[2 * H_DIM + j] = s2 * h_s[2 * H_DIM + j];
                rh_s[3 * H_DIM + j] = s3 * h_s[3 * H_DIM + j];
            } else {                   // u-gate columns 128..255
                u_s[0 * H_DIM + i] = s0;
                u_s[1 * H_DIM + i] = s1;
                u_s[2 * H_DIM + i] = s2;
                u_s[3 * H_DIM + i] = s3;
            }
            __syncthreads();

            // cand GEMM partials: k in [64*half, 64*half+64), all 4 rows
            ull c0 = 0ULL, c1 = 0ULL, c2 = 0ULL, c3 = 0ULL;
            #pragma unroll
            for (int k4 = 0; k4 < 16; k4++) {
                ulonglong2 v0 = rh20[k4];
                ffma2(c0, v0.x, wc[2 * k4]); ffma2(c0, v0.y, wc[2 * k4 + 1]);
                ulonglong2 v1 = rh21[k4];
                ffma2(c1, v1.x, wc[2 * k4]); ffma2(c1, v1.y, wc[2 * k4 + 1]);
                ulonglong2 v2 = rh22[k4];
                ffma2(c2, v2.x, wc[2 * k4]); ffma2(c2, v2.y, wc[2 * k4 + 1]);
                ulonglong2 v3 = rh23[k4];
                ffma2(c3, v3.x, wc[2 * k4]); ffma2(c3, v3.y, wc[2 * k4 + 1]);
            }
            float p0 = hsum2(c0), p1 = hsum2(c1), p2 = hsum2(c2), p3 = hsum2(c3);
            float ownA, ownB;
            if (half == 0) {           // owns rows 0,1; exports rows 2,3
                part_s[2 * H_DIM + i] = p2;
                part_s[3 * H_DIM + i] = p3;
                ownA = p0; ownB = p1;
            } else {                   // owns rows 2,3; exports rows 0,1
                part_s[0 * H_DIM + i] = p0;
                part_s[1 * H_DIM + i] = p1;
                ownA = p2; ownB = p3;
            }
            __syncthreads();

            {
                float c  = fast_tanh(ownA + part_s[(2 * half) * H_DIM + i] + vcA);
                float u  = u_s[(2 * half) * H_DIM + i];
                float hv = hA[i];
                float hn = fmaf(u, hv - c, c);   // u*h + (1-u)*c
                if (t < lenA) hA[i] = hn;
            }
            {
                float c  = fast_tanh(ownB + part_s[(2 * half + 1) * H_DIM + i] + vcB);
                float u  = u_s[(2 * half + 1) * H_DIM + i];
                float hv = hB[i];
                float hn = fmaf(u, hv - c, c);
                if (t < lenB) hB[i] = hn;
            }
            __syncthreads();
        }

        out[s_b[2 * half]     * H_DIM + i] = hA[i];
        out[s_b[2 * half + 1] * H_DIM + i] = hB[i];
        __syncthreads();
    }
}

// ---------------------------------------------------------------------------
extern "C" void kernel_launch(void* const* d_in, const int* in_sizes, int n_in,
                              void* d_out, int out_size) {
    (void)in_sizes; (void)n_in; (void)out_size;
    const int*   item_his    = (const int*)  d_in[0];
    const int*   seq_lens    = (const int*)  d_in[1];
    const float* embedding   = (const float*)d_in[2];
    const float* gate_kernel = (const float*)d_in[3];
    const float* gate_bias   = (const float*)d_in[4];
    const float* cand_kernel = (const float*)d_in[5];
    const float* cand_bias   = (const float*)d_in[6];
    float*       out         = (float*)d_out;

    const int smem_proj = (64 * XPAD + 64 * WPAD + 384) * 4;   // ~119 KB
    cudaFuncSetAttribute(proj_kernel, cudaFuncAttributeMaxDynamicSharedMemorySize, smem_proj);

    sort_kernel<<<1, 256>>>(seq_lens);
    proj_kernel<<<dim3(T_DIM / 64, B_DIM), 512, smem_proj>>>(
        item_his, seq_lens, embedding, gate_kernel, gate_bias, cand_kernel, cand_bias);
    gru_kernel<<<148, 256>>>(seq_lens, gate_kernel, cand_kernel, out);
}

// round 11
// speedup vs baseline: 1.8032x; 1.3287x over previous
#include <cuda_runtime.h>

#define B_DIM 1024
#define T_DIM 256
#define D_DIM 64
#define H_DIM 128
#define GH 256          // 2H
#define XCOLS 384       // 256 gate cols + 128 cand cols
#define RROWS 4
#define NGROUPS (B_DIM / RROWS)   // 256
#define XPAD 68         // proj x smem stride
#define WPAD 392        // proj W smem stride
#define HP 132          // gru h/rh smem row stride (conflict-free A-frag LDS)

// Scratch (device globals: no allocation allowed).
static __device__ float g_Xbuf[(size_t)B_DIM * T_DIM * XCOLS]; // ~402 MB
static __device__ int   g_perm[B_DIM];
static __device__ int   g_counter;

__device__ __forceinline__ float fast_sigmoid(float z) {
    return __fdividef(1.0f, 1.0f + __expf(-z));
}
__device__ __forceinline__ float fast_tanh(float z) {
    return 1.0f - __fdividef(2.0f, __expf(2.0f * z) + 1.0f);
}
__device__ __forceinline__ unsigned f2tf32(float f) {
    unsigned u;
    asm("cvt.rna.tf32.f32 %0, %1;" : "=r"(u) : "f"(f));
    return u;
}
__device__ __forceinline__ void mma_tf32(float& c0, float& c1, float& c2, float& c3,
                                         unsigned a0, unsigned a1, unsigned a2, unsigned a3,
                                         unsigned b0, unsigned b1) {
    asm("mma.sync.aligned.m16n8k8.row.col.f32.tf32.tf32.f32 "
        "{%0,%1,%2,%3}, {%4,%5,%6,%7}, {%8,%9}, {%0,%1,%2,%3};"
        : "+f"(c0), "+f"(c1), "+f"(c2), "+f"(c3)
        : "r"(a0), "r"(a1), "r"(a2), "r"(a3), "r"(b0), "r"(b1));
}

// ---------------------------------------------------------------------------
// K0: counting sort rows by seq_len (descending, LPT) + reset work counter.
// ---------------------------------------------------------------------------
__global__ void sort_kernel(const int* __restrict__ seq_lens) {
    __shared__ int hist[256];
    __shared__ int offs[256];
    int tid = threadIdx.x;
    hist[tid] = 0;
    __syncthreads();
    for (int r = tid; r < B_DIM; r += 256) {
        int L = seq_lens[r];
        L = min(max(L, 0), 255);
        atomicAdd(&hist[L], 1);
    }
    __syncthreads();
    if (tid == 0) {
        int run = 0;
        for (int k = 255; k >= 0; k--) { offs[k] = run; run += hist[k]; }
        g_counter = 0;
    }
    __syncthreads();
    for (int r = tid; r < B_DIM; r += 256) {
        int L = seq_lens[r];
        L = min(max(L, 0), 255);
        int pos = atomicAdd(&offs[L], 1);
        g_perm[pos] = r;
    }
}

// ---------------------------------------------------------------------------
// K1: projection via tf32 tensor cores + smem-staged coalesced epilogue.
// (unchanged from R10 — validated)
// ---------------------------------------------------------------------------
__global__ void __launch_bounds__(512) proj_kernel(
    const int* __restrict__ item_his,
    const int* __restrict__ seq_lens,
    const float* __restrict__ embedding,
    const float* __restrict__ gate_kernel,
    const float* __restrict__ gate_bias,
    const float* __restrict__ cand_kernel,
    const float* __restrict__ cand_bias)
{
    extern __shared__ unsigned smu[];
    unsigned* xs = smu;                      // [64][XPAD]
    unsigned* Wt = xs + 64 * XPAD;           // [64][WPAD] (reused as stage)
    float*    bs = (float*)(Wt + 64 * WPAD); // [384]
    __shared__ int items_s[64];

    int b  = blockIdx.y;
    int t0 = blockIdx.x * 64;
    int len = seq_lens[b];
    if (t0 >= len) return;
    int tid = threadIdx.x;

    for (int idx = tid; idx < 64 * GH; idx += 512) {
        int k = idx >> 8, c = idx & 255;
        Wt[k * WPAD + c] = f2tf32(gate_kernel[k * GH + c]);
    }
    for (int idx = tid; idx < 64 * H_DIM; idx += 512) {
        int k = idx >> 7, c = idx & 127;
        Wt[k * WPAD + 256 + c] = f2tf32(cand_kernel[k * H_DIM + c]);
    }
    if (tid < 256) bs[tid] = gate_bias[tid];
    else if (tid < 384) bs[tid] = cand_bias[tid - 256];
    if (tid < 64) items_s[tid] = item_his[b * T_DIM + t0 + tid];
    __syncthreads();

    for (int e = tid; e < 64 * 64; e += 512) {
        int rr = e >> 6, k = e & 63;
        xs[rr * XPAD + k] = f2tf32(embedding[items_s[rr] * 64 + k]);
    }
    __syncthreads();

    int warp = tid >> 5, lane = tid & 31;
    int wm = warp & 3;
    int wn = warp >> 2;
    int rbase = wm * 16;
    int nbase = wn * 96;

    float c[12][4];
    #pragma unroll
    for (int nt = 0; nt < 12; nt++)
        #pragma unroll
        for (int q = 0; q < 4; q++) c[nt][q] = 0.0f;

    int ar = rbase + (lane >> 2);
    int ac0 = lane & 3;

    #pragma unroll
    for (int k0 = 0; k0 < 8; k0++) {
        int ka = k0 * 8;
        unsigned a0 = xs[ar * XPAD + ka + ac0];
        unsigned a1 = xs[(ar + 8) * XPAD + ka + ac0];
        unsigned a2 = xs[ar * XPAD + ka + ac0 + 4];
        unsigned a3 = xs[(ar + 8) * XPAD + ka + ac0 + 4];
        const unsigned* Wrow0 = Wt + (ka + (lane & 3)) * WPAD + (lane >> 2);
        const unsigned* Wrow1 = Wrow0 + 4 * WPAD;
        #pragma unroll
        for (int nt = 0; nt < 12; nt++) {
            unsigned b0 = Wrow0[nbase + nt * 8];
            unsigned b1 = Wrow1[nbase + nt * 8];
            mma_tf32(c[nt][0], c[nt][1], c[nt][2], c[nt][3], a0, a1, a2, a3, b0, b1);
        }
    }

    __syncthreads();
    float* Xst = (float*)Wt;
    int row0 = rbase + (lane >> 2);
    #pragma unroll
    for (int nt = 0; nt < 12; nt++) {
        int col = nbase + nt * 8 + 2 * (lane & 3);
        Xst[row0 * WPAD + col]           = c[nt][0];
        Xst[row0 * WPAD + col + 1]       = c[nt][1];
        Xst[(row0 + 8) * WPAD + col]     = c[nt][2];
        Xst[(row0 + 8) * WPAD + col + 1] = c[nt][3];
    }
    __syncthreads();

    const float4* bias4 = (const float4*)bs;
    for (int rr = warp; rr < 64; rr += 16) {
        float4* dst = (float4*)(g_Xbuf + (size_t)(b * T_DIM + t0 + rr) * XCOLS);
        const float4* src = (const float4*)(Xst + rr * WPAD);
        #pragma unroll
        for (int cc = lane; cc < 96; cc += 32) {
            float4 v = src[cc], bb = bias4[cc];
            v.x += bb.x; v.y += bb.y; v.z += bb.z; v.w += bb.w;
            dst[cc] = v;
        }
    }
}

// ---------------------------------------------------------------------------
// K2: persistent GRU on TENSOR CORES (tf32 mma.sync, M=16 pad, 4 real rows).
// 256 threads = 8 warps. Warp w: gate cols [32w,32w+32) (4 n-tiles),
// cand cols [16w,16w+16) (2 n-tiles). B-fragments (weights) live in regs.
// A-fragments (h / r*h) come from smem (stride HP=132, conflict-free).
// h kept fp32 in smem; only MMA operands tf32-rounded.
// ---------------------------------------------------------------------------
__global__ void __launch_bounds__(256, 1) gru_kernel(
    const int* __restrict__ seq_lens,
    const float* __restrict__ gate_kernel,
    const float* __restrict__ cand_kernel,
    float* __restrict__ out)
{
    __shared__ float    h_s[RROWS * HP];
    __shared__ unsigned rh_t[RROWS * HP];      // tf32 bits of r*h
    __shared__ float    u_s[RROWS * H_DIM];
    __shared__ int s_g;
    __shared__ int s_b[RROWS];
    __shared__ int s_len[RROWS];

    int tid = threadIdx.x;
    int w   = tid >> 5;
    int l   = tid & 31;
    int r   = l >> 2;            // A/C fragment row (real if < 4)
    int c0  = l & 3;
    bool act = (r < RROWS);

    // ---- B-fragments in registers (one-time) ----
    // gate: 4 n-tiles x 16 k-tiles;  b0 = W[k+ c0][n], b1 = W[k+c0+4][n], n = 32w+8nt+(l>>2)
    unsigned wg0[4][16], wg1[4][16];
    #pragma unroll
    for (int nt = 0; nt < 4; nt++)
        #pragma unroll
        for (int kt = 0; kt < 16; kt++) {
            int k = D_DIM + 8 * kt + c0;
            int n = 32 * w + 8 * nt + (l >> 2);
            wg0[nt][kt] = f2tf32(gate_kernel[k * GH + n]);
            wg1[nt][kt] = f2tf32(gate_kernel[(k + 4) * GH + n]);
        }
    // cand: 2 n-tiles x 16 k-tiles
    unsigned wc0[2][16], wc1[2][16];
    #pragma unroll
    for (int nt = 0; nt < 2; nt++)
        #pragma unroll
        for (int kt = 0; kt < 16; kt++) {
            int k = D_DIM + 8 * kt + c0;
            int n = 16 * w + 8 * nt + (l >> 2);
            wc0[nt][kt] = f2tf32(cand_kernel[k * H_DIM + n]);
            wc1[nt][kt] = f2tf32(cand_kernel[(k + 4) * H_DIM + n]);
        }

    while (true) {
        if (tid == 0) s_g = atomicAdd(&g_counter, 1);
        __syncthreads();
        int g = s_g;
        if (g >= NGROUPS) break;

        if (tid < RROWS) {
            int row = g_perm[g * RROWS + tid];
            s_b[tid]   = row;
            s_len[tid] = min(max(seq_lens[row], 0), T_DIM);
        }
        for (int e = tid; e < RROWS * HP; e += 256) h_s[e] = 0.0f;
        __syncthreads();

        int L = max(max(s_len[0], s_len[1]), max(s_len[2], s_len[3]));
        int mylen = act ? s_len[r] : 0;
        int xbase = act ? s_b[r] * (T_DIM * XCOLS) : 0;
        int xg0c = 32 * w + 2 * c0;            // gate col base for this lane
        int xcc  = 256 + 16 * w + 2 * c0;      // cand col base

        for (int t = 0; t < L; t++) {
            int toff = xbase + t * XCOLS;
            // x addends (early issue; only lanes with real rows)
            float2 vg[4], vc[2];
            if (act) {
                #pragma unroll
                for (int nt = 0; nt < 4; nt++)
                    vg[nt] = *(const float2*)(g_Xbuf + toff + xg0c + 8 * nt);
                vc[0] = *(const float2*)(g_Xbuf + toff + xcc);
                vc[1] = *(const float2*)(g_Xbuf + toff + xcc + 8);
            }

            // ---- gate MMA: [16x128] h (rows 4-15 zero) x [128x32] ----
            float cg[4][4];
            #pragma unroll
            for (int nt = 0; nt < 4; nt++) { cg[nt][0]=cg[nt][1]=cg[nt][2]=cg[nt][3]=0.f; }
            #pragma unroll
            for (int kt = 0; kt < 16; kt++) {
                unsigned a0 = 0, a2 = 0;
                if (act) {
                    a0 = f2tf32(h_s[r * HP + 8 * kt + c0]);
                    a2 = f2tf32(h_s[r * HP + 8 * kt + c0 + 4]);
                }
                #pragma unroll
                for (int nt = 0; nt < 4; nt++)
                    mma_tf32(cg[nt][0], cg[nt][1], cg[nt][2], cg[nt][3],
                             a0, 0u, a2, 0u, wg0[nt][kt], wg1[nt][kt]);
            }
            if (act) {
                #pragma unroll
                for (int nt = 0; nt < 4; nt++) {
                    float s0 = fast_sigmoid(cg[nt][0] + vg[nt].x);
                    float s1 = fast_sigmoid(cg[nt][1] + vg[nt].y);
                    int col = 32 * w + 8 * nt + 2 * c0;
                    if (w < 4) {        // r-gate (cols 0..127)
                        uint2 rv;
                        rv.x = f2tf32(s0 * h_s[r * HP + col]);
                        rv.y = f2tf32(s1 * h_s[r * HP + col + 1]);
                        *(uint2*)(rh_t + r * HP + col) = rv;
                    } else {            // u-gate (cols 128..255)
                        *(float2*)(u_s + r * H_DIM + (col - 128)) = make_float2(s0, s1);
                    }
                }
            }
            __syncthreads();

            // ---- cand MMA: [16x128] r*h x [128x16] ----
            float cd[2][4];
            cd[0][0]=cd[0][1]=cd[0][2]=cd[0][3]=0.f;
            cd[1][0]=cd[1][1]=cd[1][2]=cd[1][3]=0.f;
            #pragma unroll
            for (int kt = 0; kt < 16; kt++) {
                unsigned a0 = 0, a2 = 0;
                if (act) {
                    a0 = rh_t[r * HP + 8 * kt + c0];
                    a2 = rh_t[r * HP + 8 * kt + c0 + 4];
                }
                #pragma unroll
                for (int nt = 0; nt < 2; nt++)
                    mma_tf32(cd[nt][0], cd[nt][1], cd[nt][2], cd[nt][3],
                             a0, 0u, a2, 0u, wc0[nt][kt], wc1[nt][kt]);
            }
            if (act) {
                #pragma unroll
                for (int nt = 0; nt < 2; nt++) {
                    float cc0 = fast_tanh(cd[nt][0] + vc[nt].x);
                    float cc1 = fast_tanh(cd[nt][1] + vc[nt].y);
                    int col = 16 * w + 8 * nt + 2 * c0;
                    float u0 = u_s[r * H_DIM + col];
                    float u1 = u_s[r * H_DIM + col + 1];
                    float h0 = h_s[r * HP + col];
                    float h1 = h_s[r * HP + col + 1];
                    if (t < mylen) {
                        h_s[r * HP + col]     = fmaf(u0, h0 - cc0, cc0);  // u*h+(1-u)*c
                        h_s[r * HP + col + 1] = fmaf(u1, h1 - cc1, cc1);
                    }
                }
            }
            __syncthreads();
        }

        if (act) {
            #pragma unroll
            for (int nt = 0; nt < 2; nt++) {
                int col = 16 * w + 8 * nt + 2 * c0;
                *(float2*)(out + s_b[r] * H_DIM + col) =
                    make_float2(h_s[r * HP + col], h_s[r * HP + col + 1]);
            }
        }
        __syncthreads();
    }
}

// ---------------------------------------------------------------------------
extern "C" void kernel_launch(void* const* d_in, const int* in_sizes, int n_in,
                              void* d_out, int out_size) {
    (void)in_sizes; (void)n_in; (void)out_size;
    const int*   item_his    = (const int*)  d_in[0];
    const int*   seq_lens    = (const int*)  d_in[1];
    const float* embedding   = (const float*)d_in[2];
    const float* gate_kernel = (const float*)d_in[3];
    const float* gate_bias   = (const float*)d_in[4];
    const float* cand_kernel = (const float*)d_in[5];
    const float* cand_bias   = (const float*)d_in[6];
    float*       out         = (float*)d_out;

    const int smem_proj = (64 * XPAD + 64 * WPAD + 384) * 4;   // ~119 KB
    cudaFuncSetAttribute(proj_kernel, cudaFuncAttributeMaxDynamicSharedMemorySize, smem_proj);

    sort_kernel<<<1, 256>>>(seq_lens);
    proj_kernel<<<dim3(T_DIM / 64, B_DIM), 512, smem_proj>>>(
        item_his, seq_lens, embedding, gate_kernel, gate_bias, cand_kernel, cand_bias);
    gru_kernel<<<148, 256>>>(seq_lens, gate_kernel, cand_kernel, out);
}

// round 12
// speedup vs baseline: 2.0672x; 1.1464x over previous
#include <cuda_runtime.h>
#include <cuda_fp16.h>

#define B_DIM 1024
#define T_DIM 256
#define D_DIM 64
#define H_DIM 128
#define GH 256          // 2H
#define XCOLS 384       // 256 gate cols + 128 cand cols
#define RROWS 4
#define NGROUPS (B_DIM / RROWS)   // 256
#define XPAD 68         // proj x smem stride
#define WPAD 392        // proj W smem stride
#define HP 132          // gru fp32 h row stride (floats)
#define HP2 68          // gru half2 row stride (in uint32 units; 136 halves)

// Scratch (device globals: no allocation allowed).
static __device__ float g_Xbuf[(size_t)B_DIM * T_DIM * XCOLS]; // ~402 MB
static __device__ int   g_perm[B_DIM];
static __device__ int   g_counter;

__device__ __forceinline__ float fast_sigmoid(float z) {
    return __fdividef(1.0f, 1.0f + __expf(-z));
}
__device__ __forceinline__ float fast_tanh(float z) {
    return 1.0f - __fdividef(2.0f, __expf(2.0f * z) + 1.0f);
}
__device__ __forceinline__ unsigned f2tf32(float f) {
    unsigned u;
    asm("cvt.rna.tf32.f32 %0, %1;" : "=r"(u) : "f"(f));
    return u;
}
__device__ __forceinline__ unsigned pack_h2(float lo, float hi) {
    __half2 h = __floats2half2_rn(lo, hi);
    return *(unsigned*)&h;
}
__device__ __forceinline__ void mma_tf32(float& c0, float& c1, float& c2, float& c3,
                                         unsigned a0, unsigned a1, unsigned a2, unsigned a3,
                                         unsigned b0, unsigned b1) {
    asm("mma.sync.aligned.m16n8k8.row.col.f32.tf32.tf32.f32 "
        "{%0,%1,%2,%3}, {%4,%5,%6,%7}, {%8,%9}, {%0,%1,%2,%3};"
        : "+f"(c0), "+f"(c1), "+f"(c2), "+f"(c3)
        : "r"(a0), "r"(a1), "r"(a2), "r"(a3), "r"(b0), "r"(b1));
}
__device__ __forceinline__ void mma_f16(float& c0, float& c1, float& c2, float& c3,
                                        unsigned a0, unsigned a1, unsigned a2, unsigned a3,
                                        unsigned b0, unsigned b1) {
    asm("mma.sync.aligned.m16n8k16.row.col.f32.f16.f16.f32 "
        "{%0,%1,%2,%3}, {%4,%5,%6,%7}, {%8,%9}, {%0,%1,%2,%3};"
        : "+f"(c0), "+f"(c1), "+f"(c2), "+f"(c3)
        : "r"(a0), "r"(a1), "r"(a2), "r"(a3), "r"(b0), "r"(b1));
}

// ---------------------------------------------------------------------------
// K0: counting sort rows by seq_len (descending, LPT) + reset work counter.
// ---------------------------------------------------------------------------
__global__ void sort_kernel(const int* __restrict__ seq_lens) {
    __shared__ int hist[256];
    __shared__ int offs[256];
    int tid = threadIdx.x;
    hist[tid] = 0;
    __syncthreads();
    for (int r = tid; r < B_DIM; r += 256) {
        int L = seq_lens[r];
        L = min(max(L, 0), 255);
        atomicAdd(&hist[L], 1);
    }
    __syncthreads();
    if (tid == 0) {
        int run = 0;
        for (int k = 255; k >= 0; k--) { offs[k] = run; run += hist[k]; }
        g_counter = 0;
    }
    __syncthreads();
    for (int r = tid; r < B_DIM; r += 256) {
        int L = seq_lens[r];
        L = min(max(L, 0), 255);
        int pos = atomicAdd(&offs[L], 1);
        g_perm[pos] = r;
    }
}

// ---------------------------------------------------------------------------
// K1: projection via tf32 tensor cores + smem-staged coalesced epilogue.
// (unchanged from R10 — validated)
// ---------------------------------------------------------------------------
__global__ void __launch_bounds__(512) proj_kernel(
    const int* __restrict__ item_his,
    const int* __restrict__ seq_lens,
    const float* __restrict__ embedding,
    const float* __restrict__ gate_kernel,
    const float* __restrict__ gate_bias,
    const float* __restrict__ cand_kernel,
    const float* __restrict__ cand_bias)
{
    extern __shared__ unsigned smu[];
    unsigned* xs = smu;                      // [64][XPAD]
    unsigned* Wt = xs + 64 * XPAD;           // [64][WPAD] (reused as stage)
    float*    bs = (float*)(Wt + 64 * WPAD); // [384]
    __shared__ int items_s[64];

    int b  = blockIdx.y;
    int t0 = blockIdx.x * 64;
    int len = seq_lens[b];
    if (t0 >= len) return;
    int tid = threadIdx.x;

    for (int idx = tid; idx < 64 * GH; idx += 512) {
        int k = idx >> 8, c = idx & 255;
        Wt[k * WPAD + c] = f2tf32(gate_kernel[k * GH + c]);
    }
    for (int idx = tid; idx < 64 * H_DIM; idx += 512) {
        int k = idx >> 7, c = idx & 127;
        Wt[k * WPAD + 256 + c] = f2tf32(cand_kernel[k * H_DIM + c]);
    }
    if (tid < 256) bs[tid] = gate_bias[tid];
    else if (tid < 384) bs[tid] = cand_bias[tid - 256];
    if (tid < 64) items_s[tid] = item_his[b * T_DIM + t0 + tid];
    __syncthreads();

    for (int e = tid; e < 64 * 64; e += 512) {
        int rr = e >> 6, k = e & 63;
        xs[rr * XPAD + k] = f2tf32(embedding[items_s[rr] * 64 + k]);
    }
    __syncthreads();

    int warp = tid >> 5, lane = tid & 31;
    int wm = warp & 3;
    int wn = warp >> 2;
    int rbase = wm * 16;
    int nbase = wn * 96;

    float c[12][4];
    #pragma unroll
    for (int nt = 0; nt < 12; nt++)
        #pragma unroll
        for (int q = 0; q < 4; q++) c[nt][q] = 0.0f;

    int ar = rbase + (lane >> 2);
    int ac0 = lane & 3;

    #pragma unroll
    for (int k0 = 0; k0 < 8; k0++) {
        int ka = k0 * 8;
        unsigned a0 = xs[ar * XPAD + ka + ac0];
        unsigned a1 = xs[(ar + 8) * XPAD + ka + ac0];
        unsigned a2 = xs[ar * XPAD + ka + ac0 + 4];
        unsigned a3 = xs[(ar + 8) * XPAD + ka + ac0 + 4];
        const unsigned* Wrow0 = Wt + (ka + (lane & 3)) * WPAD + (lane >> 2);
        const unsigned* Wrow1 = Wrow0 + 4 * WPAD;
        #pragma unroll
        for (int nt = 0; nt < 12; nt++) {
            unsigned b0 = Wrow0[nbase + nt * 8];
            unsigned b1 = Wrow1[nbase + nt * 8];
            mma_tf32(c[nt][0], c[nt][1], c[nt][2], c[nt][3], a0, a1, a2, a3, b0, b1);
        }
    }

    __syncthreads();
    float* Xst = (float*)Wt;
    int row0 = rbase + (lane >> 2);
    #pragma unroll
    for (int nt = 0; nt < 12; nt++) {
        int col = nbase + nt * 8 + 2 * (lane & 3);
        Xst[row0 * WPAD + col]           = c[nt][0];
        Xst[row0 * WPAD + col + 1]       = c[nt][1];
        Xst[(row0 + 8) * WPAD + col]     = c[nt][2];
        Xst[(row0 + 8) * WPAD + col + 1] = c[nt][3];
    }
    __syncthreads();

    const float4* bias4 = (const float4*)bs;
    for (int rr = warp; rr < 64; rr += 16) {
        float4* dst = (float4*)(g_Xbuf + (size_t)(b * T_DIM + t0 + rr) * XCOLS);
        const float4* src = (const float4*)(Xst + rr * WPAD);
        #pragma unroll
        for (int cc = lane; cc < 96; cc += 32) {
            float4 v = src[cc], bb = bias4[cc];
            v.x += bb.x; v.y += bb.y; v.z += bb.z; v.w += bb.w;
            dst[cc] = v;
        }
    }
}

// ---------------------------------------------------------------------------
// K2: persistent GRU on fp16 TENSOR CORES (m16n8k16, M=16 pad, 4 real rows).
// 256 threads = 8 warps. Warp w: gate cols [32w,32w+32) (4 n-tiles),
// cand cols [16w,16w+16) (2 n-tiles). B-fragments (fp16 weights) in regs.
// h kept fp32 (update) + half2 mirror (MMA operands); r*h stored half2.
// ---------------------------------------------------------------------------
__global__ void __launch_bounds__(256, 1) gru_kernel(
    const int* __restrict__ seq_lens,
    const float* __restrict__ gate_kernel,
    const float* __restrict__ cand_kernel,
    float* __restrict__ out)
{
    __shared__ float    h_s[RROWS * HP];       // fp32 master state
    __shared__ unsigned h2_s[RROWS * HP2];     // half2 mirror of h
    __shared__ unsigned rh2_s[RROWS * HP2];    // half2 of r*h
    __shared__ float    u_s[RROWS * H_DIM];
    __shared__ int s_g;
    __shared__ int s_b[RROWS];
    __shared__ int s_len[RROWS];

    int tid = threadIdx.x;
    int w   = tid >> 5;
    int l   = tid & 31;
    int r   = l >> 2;            // fragment row (real if < 4)
    int c0  = l & 3;
    bool act = (r < RROWS);

    // ---- fp16 B-fragments in registers (one-time) ----
    // m16n8k16 col-major B: lane(c0,n=l>>2): b0 = {W[16kt+2c0][n], W[16kt+2c0+1][n]},
    //                                        b1 = {W[16kt+2c0+8][n], W[16kt+2c0+9][n]}
    unsigned wg0[4][8], wg1[4][8];
    #pragma unroll
    for (int nt = 0; nt < 4; nt++)
        #pragma unroll
        for (int kt = 0; kt < 8; kt++) {
            int k = D_DIM + 16 * kt + 2 * c0;
            int n = 32 * w + 8 * nt + (l >> 2);
            wg0[nt][kt] = pack_h2(gate_kernel[k * GH + n],       gate_kernel[(k + 1) * GH + n]);
            wg1[nt][kt] = pack_h2(gate_kernel[(k + 8) * GH + n], gate_kernel[(k + 9) * GH + n]);
        }
    unsigned wc0[2][8], wc1[2][8];
    #pragma unroll
    for (int nt = 0; nt < 2; nt++)
        #pragma unroll
        for (int kt = 0; kt < 8; kt++) {
            int k = D_DIM + 16 * kt + 2 * c0;
            int n = 16 * w + 8 * nt + (l >> 2);
            wc0[nt][kt] = pack_h2(cand_kernel[k * H_DIM + n],       cand_kernel[(k + 1) * H_DIM + n]);
            wc1[nt][kt] = pack_h2(cand_kernel[(k + 8) * H_DIM + n], cand_kernel[(k + 9) * H_DIM + n]);
        }

    while (true) {
        if (tid == 0) s_g = atomicAdd(&g_counter, 1);
        __syncthreads();
        int g = s_g;
        if (g >= NGROUPS) break;

        if (tid < RROWS) {
            int row = g_perm[g * RROWS + tid];
            s_b[tid]   = row;
            s_len[tid] = min(max(seq_lens[row], 0), T_DIM);
        }
        for (int e = tid; e < RROWS * HP; e += 256) h_s[e] = 0.0f;
        for (int e = tid; e < RROWS * HP2; e += 256) h2_s[e] = 0u;
        __syncthreads();

        int L = max(max(s_len[0], s_len[1]), max(s_len[2], s_len[3]));
        int mylen = act ? s_len[r] : 0;
        int xbase = act ? s_b[r] * (T_DIM * XCOLS) : 0;
        int xg0c = 32 * w + 2 * c0;            // gate col base for this lane
        int xcc  = 256 + 16 * w + 2 * c0;      // cand col base

        for (int t = 0; t < L; t++) {
            int toff = xbase + t * XCOLS;
            float2 vg[4], vc[2];
            if (act) {
                #pragma unroll
                for (int nt = 0; nt < 4; nt++)
                    vg[nt] = *(const float2*)(g_Xbuf + toff + xg0c + 8 * nt);
                vc[0] = *(const float2*)(g_Xbuf + toff + xcc);
                vc[1] = *(const float2*)(g_Xbuf + toff + xcc + 8);
            }

            // ---- gate MMA: [16x128] h x [128x32], fp16 k16 ----
            float cg[4][4];
            #pragma unroll
            for (int nt = 0; nt < 4; nt++) { cg[nt][0]=cg[nt][1]=cg[nt][2]=cg[nt][3]=0.f; }
            #pragma unroll
            for (int kt = 0; kt < 8; kt++) {
                unsigned a0 = 0, a2 = 0;
                if (act) {
                    a0 = h2_s[r * HP2 + 8 * kt + c0];       // halves k=16kt+2c0,+1
                    a2 = h2_s[r * HP2 + 8 * kt + c0 + 4];   // halves k=16kt+2c0+8,+9
                }
                #pragma unroll
                for (int nt = 0; nt < 4; nt++)
                    mma_f16(cg[nt][0], cg[nt][1], cg[nt][2], cg[nt][3],
                            a0, 0u, a2, 0u, wg0[nt][kt], wg1[nt][kt]);
            }
            if (act) {
                #pragma unroll
                for (int nt = 0; nt < 4; nt++) {
                    float s0 = fast_sigmoid(cg[nt][0] + vg[nt].x);
                    float s1 = fast_sigmoid(cg[nt][1] + vg[nt].y);
                    int col = 32 * w + 8 * nt + 2 * c0;
                    if (w < 4) {        // r-gate (cols 0..127) -> rh half2
                        rh2_s[r * HP2 + (col >> 1)] =
                            pack_h2(s0 * h_s[r * HP + col], s1 * h_s[r * HP + col + 1]);
                    } else {            // u-gate (cols 128..255)
                        *(float2*)(u_s + r * H_DIM + (col - 128)) = make_float2(s0, s1);
                    }
                }
            }
            __syncthreads();

            // ---- cand MMA: [16x128] r*h x [128x16], fp16 k16 ----
            float cd[2][4];
            cd[0][0]=cd[0][1]=cd[0][2]=cd[0][3]=0.f;
            cd[1][0]=cd[1][1]=cd[1][2]=cd[1][3]=0.f;
            #pragma unroll
            for (int kt = 0; kt < 8; kt++) {
                unsigned a0 = 0, a2 = 0;
                if (act) {
                    a0 = rh2_s[r * HP2 + 8 * kt + c0];
                    a2 = rh2_s[r * HP2 + 8 * kt + c0 + 4];
                }
                #pragma unroll
                for (int nt = 0; nt < 2; nt++)
                    mma_f16(cd[nt][0], cd[nt][1], cd[nt][2], cd[nt][3],
                            a0, 0u, a2, 0u, wc0[nt][kt], wc1[nt][kt]);
            }
            if (act) {
                #pragma unroll
                for (int nt = 0; nt < 2; nt++) {
                    float cc0 = fast_tanh(cd[nt][0] + vc[nt].x);
                    float cc1 = fast_tanh(cd[nt][1] + vc[nt].y);
                    int col = 16 * w + 8 * nt + 2 * c0;
                    float u0 = u_s[r * H_DIM + col];
                    float u1 = u_s[r * H_DIM + col + 1];
                    float h0 = h_s[r * HP + col];
                    float h1 = h_s[r * HP + col + 1];
                    if (t < mylen) {
                        float n0 = fmaf(u0, h0 - cc0, cc0);   // u*h+(1-u)*c
                        float n1 = fmaf(u1, h1 - cc1, cc1);
                        h_s[r * HP + col]     = n0;
                        h_s[r * HP + col + 1] = n1;
                        h2_s[r * HP2 + (col >> 1)] = pack_h2(n0, n1);
                    }
                }
            }
            __syncthreads();
        }

        if (act) {
            #pragma unroll
            for (int nt = 0; nt < 2; nt++) {
                int col = 16 * w + 8 * nt + 2 * c0;
                *(float2*)(out + s_b[r] * H_DIM + col) =
                    make_float2(h_s[r * HP + col], h_s[r * HP + col + 1]);
            }
        }
        __syncthreads();
    }
}

// ---------------------------------------------------------------------------
extern "C" void kernel_launch(void* const* d_in, const int* in_sizes, int n_in,
                              void* d_out, int out_size) {
    (void)in_sizes; (void)n_in; (void)out_size;
    const int*   item_his    = (const int*)  d_in[0];
    const int*   seq_lens    = (const int*)  d_in[1];
    const float* embedding   = (const float*)d_in[2];
    const float* gate_kernel = (const float*)d_in[3];
    const float* gate_bias   = (const float*)d_in[4];
    const float* cand_kernel = (const float*)d_in[5];
    const float* cand_bias   = (const float*)d_in[6];
    float*       out         = (float*)d_out;

    const int smem_proj = (64 * XPAD + 64 * WPAD + 384) * 4;   // ~119 KB
    cudaFuncSetAttribute(proj_kernel, cudaFuncAttributeMaxDynamicSharedMemorySize, smem_proj);

    sort_kernel<<<1, 256>>>(seq_lens);
    proj_kernel<<<dim3(T_DIM / 64, B_DIM), 512, smem_proj>>>(
        item_his, seq_lens, embedding, gate_kernel, gate_bias, cand_kernel, cand_bias);
    gru_kernel<<<148, 256>>>(seq_lens, gate_kernel, cand_kernel, out);
}

// round 13
// speedup vs baseline: 2.3888x; 1.1556x over previous
#include <cuda_runtime.h>
#include <cuda_fp16.h>

#define B_DIM 1024
#define T_DIM 256
#define D_DIM 64
#define H_DIM 128
#define GH 256          // 2H
#define XCOLS 384       // 256 gate cols + 128 cand cols
#define RROWS 4
#define NGROUPS (B_DIM / RROWS)   // 256
#define XPAD 68         // proj x smem stride
#define WPAD 392        // proj W smem stride
#define HP 132          // gru fp32 h row stride (floats)
#define HP2 68          // gru half2 row stride (uint32 units)

// Scratch (device globals: no allocation allowed).
static __device__ float g_Xbuf[(size_t)B_DIM * T_DIM * XCOLS]; // ~402 MB
static __device__ int   g_perm[B_DIM];
static __device__ int   g_counter;

__device__ __forceinline__ float fast_sigmoid(float z) {
    return __fdividef(1.0f, 1.0f + __expf(-z));
}
__device__ __forceinline__ float fast_tanh(float z) {
    return 1.0f - __fdividef(2.0f, __expf(2.0f * z) + 1.0f);
}
__device__ __forceinline__ unsigned f2tf32(float f) {
    unsigned u;
    asm("cvt.rna.tf32.f32 %0, %1;" : "=r"(u) : "f"(f));
    return u;
}
__device__ __forceinline__ unsigned pack_h2(float lo, float hi) {
    __half2 h = __floats2half2_rn(lo, hi);
    return *(unsigned*)&h;
}
__device__ __forceinline__ void mma_tf32(float& c0, float& c1, float& c2, float& c3,
                                         unsigned a0, unsigned a1, unsigned a2, unsigned a3,
                                         unsigned b0, unsigned b1) {
    asm("mma.sync.aligned.m16n8k8.row.col.f32.tf32.tf32.f32 "
        "{%0,%1,%2,%3}, {%4,%5,%6,%7}, {%8,%9}, {%0,%1,%2,%3};"
        : "+f"(c0), "+f"(c1), "+f"(c2), "+f"(c3)
        : "r"(a0), "r"(a1), "r"(a2), "r"(a3), "r"(b0), "r"(b1));
}
__device__ __forceinline__ void mma_f16(float& c0, float& c1, float& c2, float& c3,
                                        unsigned a0, unsigned a1, unsigned a2, unsigned a3,
                                        unsigned b0, unsigned b1) {
    asm("mma.sync.aligned.m16n8k16.row.col.f32.f16.f16.f32 "
        "{%0,%1,%2,%3}, {%4,%5,%6,%7}, {%8,%9}, {%0,%1,%2,%3};"
        : "+f"(c0), "+f"(c1), "+f"(c2), "+f"(c3)
        : "r"(a0), "r"(a1), "r"(a2), "r"(a3), "r"(b0), "r"(b1));
}

// ---------------------------------------------------------------------------
// K0: counting sort rows by seq_len (descending, LPT) + reset work counter.
// ---------------------------------------------------------------------------
__global__ void sort_kernel(const int* __restrict__ seq_lens) {
    __shared__ int hist[256];
    __shared__ int offs[256];
    int tid = threadIdx.x;
    hist[tid] = 0;
    __syncthreads();
    for (int r = tid; r < B_DIM; r += 256) {
        int L = seq_lens[r];
        L = min(max(L, 0), 255);
        atomicAdd(&hist[L], 1);
    }
    __syncthreads();
    if (tid == 0) {
        int run = 0;
        for (int k = 255; k >= 0; k--) { offs[k] = run; run += hist[k]; }
        g_counter = 0;
    }
    __syncthreads();
    for (int r = tid; r < B_DIM; r += 256) {
        int L = seq_lens[r];
        L = min(max(L, 0), 255);
        int pos = atomicAdd(&offs[L], 1);
        g_perm[pos] = r;
    }
}

// ---------------------------------------------------------------------------
// K1: projection via tf32 tensor cores + smem-staged coalesced epilogue.
// (unchanged — validated)
// ---------------------------------------------------------------------------
__global__ void __launch_bounds__(512) proj_kernel(
    const int* __restrict__ item_his,
    const int* __restrict__ seq_lens,
    const float* __restrict__ embedding,
    const float* __restrict__ gate_kernel,
    const float* __restrict__ gate_bias,
    const float* __restrict__ cand_kernel,
    const float* __restrict__ cand_bias)
{
    extern __shared__ unsigned smu[];
    unsigned* xs = smu;                      // [64][XPAD]
    unsigned* Wt = xs + 64 * XPAD;           // [64][WPAD] (reused as stage)
    float*    bs = (float*)(Wt + 64 * WPAD); // [384]
    __shared__ int items_s[64];

    int b  = blockIdx.y;
    int t0 = blockIdx.x * 64;
    int len = seq_lens[b];
    if (t0 >= len) return;
    int tid = threadIdx.x;

    for (int idx = tid; idx < 64 * GH; idx += 512) {
        int k = idx >> 8, c = idx & 255;
        Wt[k * WPAD + c] = f2tf32(gate_kernel[k * GH + c]);
    }
    for (int idx = tid; idx < 64 * H_DIM; idx += 512) {
        int k = idx >> 7, c = idx & 127;
        Wt[k * WPAD + 256 + c] = f2tf32(cand_kernel[k * H_DIM + c]);
    }
    if (tid < 256) bs[tid] = gate_bias[tid];
    else if (tid < 384) bs[tid] = cand_bias[tid - 256];
    if (tid < 64) items_s[tid] = item_his[b * T_DIM + t0 + tid];
    __syncthreads();

    for (int e = tid; e < 64 * 64; e += 512) {
        int rr = e >> 6, k = e & 63;
        xs[rr * XPAD + k] = f2tf32(embedding[items_s[rr] * 64 + k]);
    }
    __syncthreads();

    int warp = tid >> 5, lane = tid & 31;
    int wm = warp & 3;
    int wn = warp >> 2;
    int rbase = wm * 16;
    int nbase = wn * 96;

    float c[12][4];
    #pragma unroll
    for (int nt = 0; nt < 12; nt++)
        #pragma unroll
        for (int q = 0; q < 4; q++) c[nt][q] = 0.0f;

    int ar = rbase + (lane >> 2);
    int ac0 = lane & 3;

    #pragma unroll
    for (int k0 = 0; k0 < 8; k0++) {
        int ka = k0 * 8;
        unsigned a0 = xs[ar * XPAD + ka + ac0];
        unsigned a1 = xs[(ar + 8) * XPAD + ka + ac0];
        unsigned a2 = xs[ar * XPAD + ka + ac0 + 4];
        unsigned a3 = xs[(ar + 8) * XPAD + ka + ac0 + 4];
        const unsigned* Wrow0 = Wt + (ka + (lane & 3)) * WPAD + (lane >> 2);
        const unsigned* Wrow1 = Wrow0 + 4 * WPAD;
        #pragma unroll
        for (int nt = 0; nt < 12; nt++) {
            unsigned b0 = Wrow0[nbase + nt * 8];
            unsigned b1 = Wrow1[nbase + nt * 8];
            mma_tf32(c[nt][0], c[nt][1], c[nt][2], c[nt][3], a0, a1, a2, a3, b0, b1);
        }
    }

    __syncthreads();
    float* Xst = (float*)Wt;
    int row0 = rbase + (lane >> 2);
    #pragma unroll
    for (int nt = 0; nt < 12; nt++) {
        int col = nbase + nt * 8 + 2 * (lane & 3);
        Xst[row0 * WPAD + col]           = c[nt][0];
        Xst[row0 * WPAD + col + 1]       = c[nt][1];
        Xst[(row0 + 8) * WPAD + col]     = c[nt][2];
        Xst[(row0 + 8) * WPAD + col + 1] = c[nt][3];
    }
    __syncthreads();

    const float4* bias4 = (const float4*)bs;
    for (int rr = warp; rr < 64; rr += 16) {
        float4* dst = (float4*)(g_Xbuf + (size_t)(b * T_DIM + t0 + rr) * XCOLS);
        const float4* src = (const float4*)(Xst + rr * WPAD);
        #pragma unroll
        for (int cc = lane; cc < 96; cc += 32) {
            float4 v = src[cc], bb = bias4[cc];
            v.x += bb.x; v.y += bb.y; v.z += bb.z; v.w += bb.w;
            dst[cc] = v;
        }
    }
}

// ---------------------------------------------------------------------------
// K2: persistent GRU on fp16 tensor cores — 512 threads (16 warps, 4/SMSP).
// Warp w: gate cols [16w,16w+16) (2 n-tiles), cand cols [8w,8w+8) (1 n-tile).
// B-fragments in registers; h fp32 + half2 mirror; x-addends prefetched
// one step ahead (software pipeline across both barriers).
// ---------------------------------------------------------------------------
__global__ void __launch_bounds__(512, 1) gru_kernel(
    const int* __restrict__ seq_lens,
    const float* __restrict__ gate_kernel,
    const float* __restrict__ cand_kernel,
    float* __restrict__ out)
{
    __shared__ float    h_s[RROWS * HP];       // fp32 master state
    __shared__ unsigned h2_s[RROWS * HP2];     // half2 mirror of h
    __shared__ unsigned rh2_s[RROWS * HP2];    // half2 of r*h
    __shared__ float    u_s[RROWS * H_DIM];
    __shared__ int s_g;
    __shared__ int s_b[RROWS];
    __shared__ int s_len[RROWS];

    int tid = threadIdx.x;
    int w   = tid >> 5;          // 0..15
    int l   = tid & 31;
    int r   = l >> 2;            // fragment row (real if < 4)
    int c0  = l & 3;
    bool act = (r < RROWS);

    // ---- fp16 B-fragments in registers (one-time) ----
    unsigned wg0[2][8], wg1[2][8];
    #pragma unroll
    for (int nt = 0; nt < 2; nt++)
        #pragma unroll
        for (int kt = 0; kt < 8; kt++) {
            int k = D_DIM + 16 * kt + 2 * c0;
            int n = 16 * w + 8 * nt + (l >> 2);
            wg0[nt][kt] = pack_h2(gate_kernel[k * GH + n],       gate_kernel[(k + 1) * GH + n]);
            wg1[nt][kt] = pack_h2(gate_kernel[(k + 8) * GH + n], gate_kernel[(k + 9) * GH + n]);
        }
    unsigned wc0[8], wc1[8];
    #pragma unroll
    for (int kt = 0; kt < 8; kt++) {
        int k = D_DIM + 16 * kt + 2 * c0;
        int n = 8 * w + (l >> 2);
        wc0[kt] = pack_h2(cand_kernel[k * H_DIM + n],       cand_kernel[(k + 1) * H_DIM + n]);
        wc1[kt] = pack_h2(cand_kernel[(k + 8) * H_DIM + n], cand_kernel[(k + 9) * H_DIM + n]);
    }

    while (true) {
        if (tid == 0) s_g = atomicAdd(&g_counter, 1);
        __syncthreads();
        int g = s_g;
        if (g >= NGROUPS) break;

        if (tid < RROWS) {
            int row = g_perm[g * RROWS + tid];
            s_b[tid]   = row;
            s_len[tid] = min(max(seq_lens[row], 0), T_DIM);
        }
        for (int e = tid; e < RROWS * HP; e += 512) h_s[e] = 0.0f;
        for (int e = tid; e < RROWS * HP2; e += 512) h2_s[e] = 0u;
        __syncthreads();

        int L = max(max(s_len[0], s_len[1]), max(s_len[2], s_len[3]));
        int mylen = act ? s_len[r] : 0;
        int xbase = act ? s_b[r] * (T_DIM * XCOLS) : 0;
        int xg0c = 16 * w + 2 * c0;            // gate col base for this lane
        int xcc  = 256 + 8 * w + 2 * c0;       // cand col base
        int colc = 8 * w + 2 * c0;             // cand/h update col

        // preload x for t = 0
        float2 vg0 = make_float2(0.f, 0.f), vg1 = vg0, vc = vg0;
        if (act && L > 0) {
            vg0 = *(const float2*)(g_Xbuf + xbase + xg0c);
            vg1 = *(const float2*)(g_Xbuf + xbase + xg0c + 8);
            vc  = *(const float2*)(g_Xbuf + xbase + xcc);
        }

        for (int t = 0; t < L; t++) {
            // prefetch x for t+1 (hidden behind this step's compute)
            float2 nvg0 = vg0, nvg1 = vg1, nvc = vc;
            if (act && t + 1 < L) {
                int toff2 = xbase + (t + 1) * XCOLS;
                nvg0 = *(const float2*)(g_Xbuf + toff2 + xg0c);
                nvg1 = *(const float2*)(g_Xbuf + toff2 + xg0c + 8);
                nvc  = *(const float2*)(g_Xbuf + toff2 + xcc);
            }

            // ---- gate MMA: [16x128] h x [128x16], fp16 k16 ----
            float cg[2][4];
            cg[0][0]=cg[0][1]=cg[0][2]=cg[0][3]=0.f;
            cg[1][0]=cg[1][1]=cg[1][2]=cg[1][3]=0.f;
            #pragma unroll
            for (int kt = 0; kt < 8; kt++) {
                unsigned a0 = 0, a2 = 0;
                if (act) {
                    a0 = h2_s[r * HP2 + 8 * kt + c0];
                    a2 = h2_s[r * HP2 + 8 * kt + c0 + 4];
                }
                #pragma unroll
                for (int nt = 0; nt < 2; nt++)
                    mma_f16(cg[nt][0], cg[nt][1], cg[nt][2], cg[nt][3],
                            a0, 0u, a2, 0u, wg0[nt][kt], wg1[nt][kt]);
            }
            if (act) {
                float s0a = fast_sigmoid(cg[0][0] + vg0.x);
                float s1a = fast_sigmoid(cg[0][1] + vg0.y);
                float s0b = fast_sigmoid(cg[1][0] + vg1.x);
                float s1b = fast_sigmoid(cg[1][1] + vg1.y);
                int colA = 16 * w + 2 * c0;
                int colB = colA + 8;
                if (w < 8) {        // r-gate (cols 0..127)
                    rh2_s[r * HP2 + (colA >> 1)] =
                        pack_h2(s0a * h_s[r * HP + colA], s1a * h_s[r * HP + colA + 1]);
                    rh2_s[r * HP2 + (colB >> 1)] =
                        pack_h2(s0b * h_s[r * HP + colB], s1b * h_s[r * HP + colB + 1]);
                } else {            // u-gate (cols 128..255)
                    *(float2*)(u_s + r * H_DIM + (colA - 128)) = make_float2(s0a, s1a);
                    *(float2*)(u_s + r * H_DIM + (colB - 128)) = make_float2(s0b, s1b);
                }
            }
            __syncthreads();

            // ---- cand MMA: [16x128] r*h x [128x8], fp16 k16 ----
            float cd[4];
            cd[0]=cd[1]=cd[2]=cd[3]=0.f;
            #pragma unroll
            for (int kt = 0; kt < 8; kt++) {
                unsigned a0 = 0, a2 = 0;
                if (act) {
                    a0 = rh2_s[r * HP2 + 8 * kt + c0];
                    a2 = rh2_s[r * HP2 + 8 * kt + c0 + 4];
                }
                mma_f16(cd[0], cd[1], cd[2], cd[3],
                        a0, 0u, a2, 0u, wc0[kt], wc1[kt]);
            }
            if (act) {
                float cc0 = fast_tanh(cd[0] + vc.x);
                float cc1 = fast_tanh(cd[1] + vc.y);
                float u0 = u_s[r * H_DIM + colc];
                float u1 = u_s[r * H_DIM + colc + 1];
                float h0 = h_s[r * HP + colc];
                float h1 = h_s[r * HP + colc + 1];
                if (t < mylen) {
                    float n0 = fmaf(u0, h0 - cc0, cc0);   // u*h+(1-u)*c
                    float n1 = fmaf(u1, h1 - cc1, cc1);
                    h_s[r * HP + colc]     = n0;
                    h_s[r * HP + colc + 1] = n1;
                    h2_s[r * HP2 + (colc >> 1)] = pack_h2(n0, n1);
                }
            }
            __syncthreads();

            vg0 = nvg0; vg1 = nvg1; vc = nvc;
        }

        if (act) {
            *(float2*)(out + s_b[r] * H_DIM + colc) =
                make_float2(h_s[r * HP + colc], h_s[r * HP + colc + 1]);
        }
        __syncthreads();
    }
}

// ---------------------------------------------------------------------------
extern "C" void kernel_launch(void* const* d_in, const int* in_sizes, int n_in,
                              void* d_out, int out_size) {
    (void)in_sizes; (void)n_in; (void)out_size;
    const int*   item_his    = (const int*)  d_in[0];
    const int*   seq_lens    = (const int*)  d_in[1];
    const float* embedding   = (const float*)d_in[2];
    const float* gate_kernel = (const float*)d_in[3];
    const float* gate_bias   = (const float*)d_in[4];
    const float* cand_kernel = (const float*)d_in[5];
    const float* cand_bias   = (const float*)d_in[6];
    float*       out         = (float*)d_out;

    const int smem_proj = (64 * XPAD + 64 * WPAD + 384) * 4;   // ~119 KB
    cudaFuncSetAttribute(proj_kernel, cudaFuncAttributeMaxDynamicSharedMemorySize, smem_proj);

    sort_kernel<<<1, 256>>>(seq_lens);
    proj_kernel<<<dim3(T_DIM / 64, B_DIM), 512, smem_proj>>>(
        item_his, seq_lens, embedding, gate_kernel, gate_bias, cand_kernel, cand_bias);
    gru_kernel<<<148, 512>>>(seq_lens, gate_kernel, cand_kernel, out);
}